// round 7
// baseline (speedup 1.0000x reference)
#include <cuda_runtime.h>
#include <cuda_bf16.h>
#include <cstdint>

#define B_ 8
#define T_ 2048
#define C_ 1024
#define H_ 64
#define NROW (B_*T_)
#define PK 40   // proj smem k-stride (bf16) — 80B, ldmatrix conflict-free
#define PT 72   // flash smem stride (bf16) — 144B, ldmatrix conflict-free

__device__ __nv_bfloat16 g_wh[192*C_];   // [n][k]
__device__ __nv_bfloat16 g_wl[192*C_];
__device__ __nv_bfloat16 g_qh[NROW*H_];
__device__ __nv_bfloat16 g_ql[NROW*H_];
__device__ __nv_bfloat16 g_kh[NROW*H_];
__device__ __nv_bfloat16 g_kl[NROW*H_];
__device__ __nv_bfloat16 g_vh[B_*H_*T_];   // [b][h][t]
__device__ __nv_bfloat16 g_vl[B_*H_*T_];

__device__ float g_Om[2][NROW*H_];
__device__ float g_m[2][NROW];
__device__ float g_l[2][NROW];

// ---------------------------------------------------------------------------
__device__ __forceinline__ void mma_bf16(float* c, const uint32_t* a,
                                         uint32_t b0, uint32_t b1) {
    asm volatile("mma.sync.aligned.m16n8k16.row.col.f32.bf16.bf16.f32 "
        "{%0,%1,%2,%3}, {%4,%5,%6,%7}, {%8,%9}, {%0,%1,%2,%3};"
        : "+f"(c[0]), "+f"(c[1]), "+f"(c[2]), "+f"(c[3])
        : "r"(a[0]), "r"(a[1]), "r"(a[2]), "r"(a[3]), "r"(b0), "r"(b1));
}
__device__ __forceinline__ void ldm4(uint32_t* r, uint32_t addr) {
    asm volatile("ldmatrix.sync.aligned.m8n8.x4.shared.b16 {%0,%1,%2,%3}, [%4];"
        : "=r"(r[0]), "=r"(r[1]), "=r"(r[2]), "=r"(r[3]) : "r"(addr));
}
__device__ __forceinline__ void split1(float v, __nv_bfloat16& h, __nv_bfloat16& l) {
    h = __float2bfloat16_rn(v);
    l = __float2bfloat16_rn(v - __bfloat162float(h));
}
__device__ __forceinline__ uint32_t packb(__nv_bfloat16 e0, __nv_bfloat16 e1) {
    return (uint32_t)__bfloat16_as_ushort(e0) |
           ((uint32_t)__bfloat16_as_ushort(e1) << 16);
}
__device__ __forceinline__ void split_pack(float a, float b, uint32_t& hi, uint32_t& lo) {
    __nv_bfloat16 ah, al, bh, bl;
    split1(a, ah, al); split1(b, bh, bl);
    hi = packb(ah, bh); lo = packb(al, bl);
}
__device__ __forceinline__ uint32_t s2u(const void* p) {
    uint32_t a;
    asm("{ .reg .u64 t; cvta.to.shared.u64 t, %1; cvt.u32.u64 %0, t; }" : "=r"(a) : "l"(p));
    return a;
}
__device__ __forceinline__ void cpa16(uint32_t dst, const void* src) {
    asm volatile("cp.async.cg.shared.global [%0], [%1], 16;" :: "r"(dst), "l"(src) : "memory");
}
#define CP_COMMIT() asm volatile("cp.async.commit_group;" ::: "memory")
#define CP_WAIT1()  asm volatile("cp.async.wait_group 1;" ::: "memory")
#define CP_WAIT0()  asm volatile("cp.async.wait_group 0;" ::: "memory")

// ---------------------------------------------------------------------------
// Kernel 0: split W into bf16 hi/lo, transposed to [n][k].
// ---------------------------------------------------------------------------
__global__ void wconv(const float* __restrict__ Wk, const float* __restrict__ Wq,
                      const float* __restrict__ Wv)
{
    int slot = blockIdx.x * 256 + threadIdx.x;
    int k  = slot >> 4;
    int nq = (slot & 15) * 4;
    int mat = k >> 10;
    int kk = k & 1023;
    const float* W = (mat == 0) ? Wq : ((mat == 1) ? Wk : Wv);
    float4 v = *(const float4*)(W + (size_t)kk * H_ + nq);
    float f[4] = { v.x, v.y, v.z, v.w };
#pragma unroll
    for (int j = 0; j < 4; j++) {
        __nv_bfloat16 h, l; split1(f[j], h, l);
        size_t o = (size_t)(mat * 64 + nq + j) * C_ + kk;
        g_wh[o] = h; g_wl[o] = l;
    }
}

// ---------------------------------------------------------------------------
// Kernel 1: QKV projection, ldmatrix fragment loads.
// ---------------------------------------------------------------------------
struct ProjS {
    __nv_bfloat16 xh[2][64*PK];
    __nv_bfloat16 xl[2][64*PK];
    __nv_bfloat16 wh[2][192*PK];
    __nv_bfloat16 wl[2][192*PK];
};

__global__ __launch_bounds__(256, 2) void qkv_proj(const float* __restrict__ x)
{
    extern __shared__ char smraw[];
    ProjS* sm = reinterpret_cast<ProjS*>(smraw);
    const int tid = threadIdx.x, lane = tid & 31, wid = tid >> 5;
    const int g = lane >> 2, tg = lane & 3;
    const int m0 = 32 * (wid >> 2);
    const int n0 = 48 * (wid & 3);
    const size_t rowBase = (size_t)blockIdx.x * 64;

    // ldmatrix lane address components
    const int arow = (lane & 7) + ((lane >> 3) & 1) * 8;   // A: m-row within 16
    const int acol = ((lane >> 4) & 1) * 8;                // A: k offset (bf16)
    const int brow = (lane & 7) + ((lane >> 4) & 1) * 8;   // B: n-row within 16
    const int bcol = ((lane >> 3) & 1) * 8;                // B: k offset (bf16)

    float acc[2][6][4];
#pragma unroll
    for (int a = 0; a < 2; a++)
#pragma unroll
        for (int b = 0; b < 6; b++)
#pragma unroll
            for (int c = 0; c < 4; c++) acc[a][b][c] = 0.0f;

#pragma unroll
    for (int i = 0; i < 3; i++) {
        int slot = tid + 256*i; int n = slot >> 2; int c8 = (slot & 3) * 8;
        cpa16(s2u(&sm->wh[0][n*PK + c8]), g_wh + (size_t)n * C_ + c8);
        cpa16(s2u(&sm->wl[0][n*PK + c8]), g_wl + (size_t)n * C_ + c8);
    }
    CP_COMMIT();
    float4 xr[2];
#pragma unroll
    for (int i = 0; i < 2; i++) {
        int slot = tid + 256*i; int r = slot >> 3; int c = (slot & 7) * 4;
        xr[i] = *(const float4*)(x + (rowBase + r) * C_ + c);
    }

    for (int it = 0; it < 32; ++it) {
        const int s = it & 1;
#pragma unroll
        for (int i = 0; i < 2; i++) {
            int slot = tid + 256*i; int r = slot >> 3; int c = (slot & 7) * 4;
            uint32_t h0, l0, h1, l1;
            split_pack(xr[i].x, xr[i].y, h0, l0);
            split_pack(xr[i].z, xr[i].w, h1, l1);
            uint2 ph = { h0, h1 }, pl = { l0, l1 };
            *reinterpret_cast<uint2*>(&sm->xh[s][r*PK + c]) = ph;
            *reinterpret_cast<uint2*>(&sm->xl[s][r*PK + c]) = pl;
        }
        if (it < 31) {
            const int kt = (it + 1) * 32;
#pragma unroll
            for (int i = 0; i < 3; i++) {
                int slot = tid + 256*i; int n = slot >> 2; int c8 = (slot & 3) * 8;
                cpa16(s2u(&sm->wh[1-s][n*PK + c8]), g_wh + (size_t)n * C_ + kt + c8);
                cpa16(s2u(&sm->wl[1-s][n*PK + c8]), g_wl + (size_t)n * C_ + kt + c8);
            }
        }
        CP_COMMIT();
        CP_WAIT1();
        __syncthreads();

        if (it < 31) {
            const int kt = (it + 1) * 32;
#pragma unroll
            for (int i = 0; i < 2; i++) {
                int slot = tid + 256*i; int r = slot >> 3; int c = (slot & 7) * 4;
                xr[i] = *(const float4*)(x + (rowBase + r) * C_ + kt + c);
            }
        }

#pragma unroll
        for (int ks = 0; ks < 2; ks++) {
            uint32_t ah[2][4], al[2][4];
#pragma unroll
            for (int mt = 0; mt < 2; mt++) {
                int base = (m0 + 16*mt + arow)*PK + ks*16 + acol;
                ldm4(ah[mt], s2u(&sm->xh[s][base]));
                ldm4(al[mt], s2u(&sm->xl[s][base]));
            }
#pragma unroll
            for (int np = 0; np < 3; np++) {
                int bbase = (n0 + 16*np + brow)*PK + ks*16 + bcol;
                uint32_t bh[4], bl[4];
                ldm4(bh, s2u(&sm->wh[s][bbase]));
                ldm4(bl, s2u(&sm->wl[s][bbase]));
#pragma unroll
                for (int sub = 0; sub < 2; sub++) {
                    int nt = 2*np + sub;
#pragma unroll
                    for (int mt = 0; mt < 2; mt++) {
                        mma_bf16(acc[mt][nt], ah[mt], bh[2*sub], bh[2*sub+1]);
                        mma_bf16(acc[mt][nt], ah[mt], bl[2*sub], bl[2*sub+1]);
                        mma_bf16(acc[mt][nt], al[mt], bh[2*sub], bh[2*sub+1]);
                    }
                }
            }
        }
        __syncthreads();
    }

    const float qscale = 0.03125f;
#pragma unroll
    for (int mt = 0; mt < 2; mt++) {
#pragma unroll
        for (int nt = 0; nt < 6; nt++) {
            int gc = n0 + 8*nt;
            float* c = acc[mt][nt];
            int r0 = m0 + 16*mt + g;
            size_t row0 = rowBase + r0, row1 = row0 + 8;
            if (gc < 64) {
                int col = gc + 2*tg;
                uint32_t h, l;
                split_pack(c[0]*qscale, c[1]*qscale, h, l);
                *reinterpret_cast<uint32_t*>(&g_qh[row0*H_ + col]) = h;
                *reinterpret_cast<uint32_t*>(&g_ql[row0*H_ + col]) = l;
                split_pack(c[2]*qscale, c[3]*qscale, h, l);
                *reinterpret_cast<uint32_t*>(&g_qh[row1*H_ + col]) = h;
                *reinterpret_cast<uint32_t*>(&g_ql[row1*H_ + col]) = l;
            } else if (gc < 128) {
                int col = gc - 64 + 2*tg;
                uint32_t h, l;
                split_pack(c[0], c[1], h, l);
                *reinterpret_cast<uint32_t*>(&g_kh[row0*H_ + col]) = h;
                *reinterpret_cast<uint32_t*>(&g_kl[row0*H_ + col]) = l;
                split_pack(c[2], c[3], h, l);
                *reinterpret_cast<uint32_t*>(&g_kh[row1*H_ + col]) = h;
                *reinterpret_cast<uint32_t*>(&g_kl[row1*H_ + col]) = l;
            } else {
                int h0 = gc - 128 + 2*tg;
                size_t bb = rowBase >> 11;
                size_t tb = (rowBase & 2047);
                __nv_bfloat16 hh, ll;
                split1(c[0], hh, ll);
                g_vh[(bb*H_ + h0    )*T_ + tb + r0] = hh;
                g_vl[(bb*H_ + h0    )*T_ + tb + r0] = ll;
                split1(c[1], hh, ll);
                g_vh[(bb*H_ + h0 + 1)*T_ + tb + r0] = hh;
                g_vl[(bb*H_ + h0 + 1)*T_ + tb + r0] = ll;
                split1(c[2], hh, ll);
                g_vh[(bb*H_ + h0    )*T_ + tb + r0 + 8] = hh;
                g_vl[(bb*H_ + h0    )*T_ + tb + r0 + 8] = ll;
                split1(c[3], hh, ll);
                g_vh[(bb*H_ + h0 + 1)*T_ + tb + r0 + 8] = hh;
                g_vl[(bb*H_ + h0 + 1)*T_ + tb + r0 + 8] = ll;
            }
        }
    }
}

// ---------------------------------------------------------------------------
// Kernel 2: split-KV causal flash attention, ldmatrix fragment loads.
// ---------------------------------------------------------------------------
struct FaS {
    __nv_bfloat16 qh[64*PT], ql[64*PT];
    __nv_bfloat16 kh[2][64*PT], kl[2][64*PT];
    __nv_bfloat16 vh[2][64*PT], vl[2][64*PT];
};

__global__ __launch_bounds__(128) void flash_mma()
{
    extern __shared__ char smraw[];
    FaS* sm = reinterpret_cast<FaS*>(smraw);
    const int tid = threadIdx.x, lane = tid & 31;
    const int g = lane >> 2, tg = lane & 3;
    const int m0 = 16 * (tid >> 5);
    const int blk = blockIdx.x;
    const int h    = blk & 1;
    const int rest = blk >> 1;
    const int qt = 31 - (rest >> 3);
    const int b  = rest & 7;
    const int ntiles = (qt >= h) ? ((qt - h) >> 1) + 1 : 0;

    const int arow = (lane & 7) + ((lane >> 3) & 1) * 8;
    const int acol = ((lane >> 4) & 1) * 8;
    const int brow = (lane & 7) + ((lane >> 4) & 1) * 8;
    const int bcol = ((lane >> 3) & 1) * 8;

    const __nv_bfloat16* khb = g_kh + (size_t)b*T_*H_;
    const __nv_bfloat16* klb = g_kl + (size_t)b*T_*H_;
    const __nv_bfloat16* vhb = g_vh + (size_t)b*H_*T_;
    const __nv_bfloat16* vlb = g_vl + (size_t)b*H_*T_;

    {
        const __nv_bfloat16* sh = g_qh + (size_t)(b*T_ + qt*64) * H_;
        const __nv_bfloat16* sl = g_ql + (size_t)(b*T_ + qt*64) * H_;
        const int t0 = h * 64;
#pragma unroll
        for (int i = 0; i < 4; i++) {
            int slot = tid + 128*i; int r = slot >> 3; int c = (slot & 7) * 8;
            cpa16(s2u(&sm->qh[r*PT + c]), sh + r*H_ + c);
            cpa16(s2u(&sm->ql[r*PT + c]), sl + r*H_ + c);
            if (ntiles > 0) {
                cpa16(s2u(&sm->kh[0][r*PT + c]), khb + (size_t)(t0 + r)*H_ + c);
                cpa16(s2u(&sm->kl[0][r*PT + c]), klb + (size_t)(t0 + r)*H_ + c);
                cpa16(s2u(&sm->vh[0][r*PT + c]), vhb + (size_t)r*T_ + t0 + c);
                cpa16(s2u(&sm->vl[0][r*PT + c]), vlb + (size_t)r*T_ + t0 + c);
            }
        }
        CP_COMMIT();
    }

    float O[8][4];
#pragma unroll
    for (int a = 0; a < 8; a++)
#pragma unroll
        for (int c = 0; c < 4; c++) O[a][c] = 0.0f;
    float mr[2] = { -1e30f, -1e30f }, lr[2] = { 0.0f, 0.0f };

    for (int i = 0; i < ntiles; ++i) {
        const int kvt = h + 2*i;
        const int s = i & 1;
        __syncthreads();
        if (i + 1 < ntiles) {
            const int nt4 = (kvt + 2) * 64;
#pragma unroll
            for (int j = 0; j < 4; j++) {
                int slot = tid + 128*j; int r = slot >> 3; int c = (slot & 7) * 8;
                cpa16(s2u(&sm->kh[1-s][r*PT + c]), khb + (size_t)(nt4 + r)*H_ + c);
                cpa16(s2u(&sm->kl[1-s][r*PT + c]), klb + (size_t)(nt4 + r)*H_ + c);
                cpa16(s2u(&sm->vh[1-s][r*PT + c]), vhb + (size_t)r*T_ + nt4 + c);
                cpa16(s2u(&sm->vl[1-s][r*PT + c]), vlb + (size_t)r*T_ + nt4 + c);
            }
        }
        CP_COMMIT();
        CP_WAIT1();
        __syncthreads();

        float Sf[8][4];
#pragma unroll
        for (int a = 0; a < 8; a++)
#pragma unroll
            for (int c = 0; c < 4; c++) Sf[a][c] = 0.0f;

#pragma unroll
        for (int ks = 0; ks < 4; ks++) {
            int abase = (m0 + arow)*PT + ks*16 + acol;
            uint32_t ah[4], al[4];
            ldm4(ah, s2u(&sm->qh[abase]));
            ldm4(al, s2u(&sm->ql[abase]));
#pragma unroll
            for (int np = 0; np < 4; np++) {
                int bbase = (16*np + brow)*PT + ks*16 + bcol;
                uint32_t bh[4], bl[4];
                ldm4(bh, s2u(&sm->kh[s][bbase]));
                ldm4(bl, s2u(&sm->kl[s][bbase]));
#pragma unroll
                for (int sub = 0; sub < 2; sub++) {
                    int nt = 2*np + sub;
                    mma_bf16(Sf[nt], ah, bh[2*sub], bh[2*sub+1]);
                    mma_bf16(Sf[nt], ah, bl[2*sub], bl[2*sub+1]);
                    mma_bf16(Sf[nt], al, bh[2*sub], bh[2*sub+1]);
                }
            }
        }

        if (kvt == qt) {
#pragma unroll
            for (int nt = 0; nt < 8; nt++) {
                int colb = 8*nt + 2*tg;
                int row0 = m0 + g, row1 = row0 + 8;
                if (colb     > row0) Sf[nt][0] = -1e30f;
                if (colb + 1 > row0) Sf[nt][1] = -1e30f;
                if (colb     > row1) Sf[nt][2] = -1e30f;
                if (colb + 1 > row1) Sf[nt][3] = -1e30f;
            }
        }

#pragma unroll
        for (int rr = 0; rr < 2; rr++) {
            float mx = -1e30f;
#pragma unroll
            for (int nt = 0; nt < 8; nt++)
                mx = fmaxf(mx, fmaxf(Sf[nt][2*rr], Sf[nt][2*rr+1]));
            mx = fmaxf(mx, __shfl_xor_sync(0xffffffffu, mx, 1));
            mx = fmaxf(mx, __shfl_xor_sync(0xffffffffu, mx, 2));
            float mn = fmaxf(mr[rr], mx);
            float corr = __expf(mr[rr] - mn);
            mr[rr] = mn;
            float sum = 0.0f;
#pragma unroll
            for (int nt = 0; nt < 8; nt++) {
                float p0 = __expf(Sf[nt][2*rr]   - mn);
                float p1 = __expf(Sf[nt][2*rr+1] - mn);
                Sf[nt][2*rr] = p0; Sf[nt][2*rr+1] = p1;
                sum += p0 + p1;
            }
            sum += __shfl_xor_sync(0xffffffffu, sum, 1);
            sum += __shfl_xor_sync(0xffffffffu, sum, 2);
            lr[rr] = lr[rr]*corr + sum;
#pragma unroll
            for (int nt = 0; nt < 8; nt++) {
                O[nt][2*rr]   *= corr;
                O[nt][2*rr+1] *= corr;
            }
        }

#pragma unroll
        for (int ks = 0; ks < 4; ks++) {
            uint32_t ph[4], pl[4];
            split_pack(Sf[2*ks][0],   Sf[2*ks][1],   ph[0], pl[0]);
            split_pack(Sf[2*ks][2],   Sf[2*ks][3],   ph[1], pl[1]);
            split_pack(Sf[2*ks+1][0], Sf[2*ks+1][1], ph[2], pl[2]);
            split_pack(Sf[2*ks+1][2], Sf[2*ks+1][3], ph[3], pl[3]);
#pragma unroll
            for (int np = 0; np < 4; np++) {
                int bbase = (16*np + brow)*PT + ks*16 + bcol;
                uint32_t bh[4], bl[4];
                ldm4(bh, s2u(&sm->vh[s][bbase]));
                ldm4(bl, s2u(&sm->vl[s][bbase]));
#pragma unroll
                for (int sub = 0; sub < 2; sub++) {
                    int nt = 2*np + sub;
                    mma_bf16(O[nt], ph, bh[2*sub], bh[2*sub+1]);
                    mma_bf16(O[nt], ph, bl[2*sub], bl[2*sub+1]);
                    mma_bf16(O[nt], pl, bh[2*sub], bh[2*sub+1]);
                }
            }
        }
    }

    CP_WAIT0();

    size_t row0 = (size_t)b*T_ + (size_t)qt*64 + m0 + g;
    size_t row1 = row0 + 8;
    float* Od = g_Om[h];
#pragma unroll
    for (int nt = 0; nt < 8; nt++) {
        int col = 8*nt + 2*tg;
        float2 v0 = { O[nt][0], O[nt][1] };
        float2 v1 = { O[nt][2], O[nt][3] };
        *reinterpret_cast<float2*>(Od + row0*H_ + col) = v0;
        *reinterpret_cast<float2*>(Od + row1*H_ + col) = v1;
    }
    if (tg == 0) {
        g_m[h][row0] = mr[0]; g_l[h][row0] = lr[0];
        g_m[h][row1] = mr[1]; g_l[h][row1] = lr[1];
    }
}

// ---------------------------------------------------------------------------
// Kernel 3: merge the two split-KV partials.
// ---------------------------------------------------------------------------
__global__ __launch_bounds__(256) void fa_merge(float* __restrict__ out)
{
    int idx = blockIdx.x * 256 + threadIdx.x;
    int row = idx >> 4;
    int c4  = (idx & 15) * 4;
    float m0v = g_m[0][row], m1v = g_m[1][row];
    float l0v = g_l[0][row], l1v = g_l[1][row];
    float M = fmaxf(m0v, m1v);
    float a0 = __expf(m0v - M), a1 = __expf(m1v - M);
    float denom = l0v * a0 + l1v * a1;
    float inv = 1.0f / denom;
    float4 o0 = *reinterpret_cast<const float4*>(&g_Om[0][(size_t)row*H_ + c4]);
    float4 o1 = *reinterpret_cast<const float4*>(&g_Om[1][(size_t)row*H_ + c4]);
    float4 r;
    r.x = (o0.x*a0 + o1.x*a1) * inv;
    r.y = (o0.y*a0 + o1.y*a1) * inv;
    r.z = (o0.z*a0 + o1.z*a1) * inv;
    r.w = (o0.w*a0 + o1.w*a1) * inv;
    *reinterpret_cast<float4*>(out + (size_t)row*H_ + c4) = r;
}

// ---------------------------------------------------------------------------
extern "C" void kernel_launch(void* const* d_in, const int* in_sizes, int n_in,
                              void* d_out, int out_size)
{
    const float* x  = (const float*)d_in[0];
    const float* Wk = (const float*)d_in[1];
    const float* Wq = (const float*)d_in[2];
    const float* Wv = (const float*)d_in[3];
    float* out = (float*)d_out;

    wconv<<<192, 256>>>(Wk, Wq, Wv);

    const int psm = (int)sizeof(ProjS);   // 81920
    cudaFuncSetAttribute(qkv_proj, cudaFuncAttributeMaxDynamicSharedMemorySize, psm);
    qkv_proj<<<NROW / 64, 256, psm>>>(x);

    const int fsm = (int)sizeof(FaS);     // 92160
    cudaFuncSetAttribute(flash_mma, cudaFuncAttributeMaxDynamicSharedMemorySize, fsm);
    flash_mma<<<(T_/64) * B_ * 2, 128, fsm>>>();

    fa_merge<<<NROW * H_ / 4 / 256, 256>>>(out);
}

// round 8
// speedup vs baseline: 1.0270x; 1.0270x over previous
#include <cuda_runtime.h>
#include <cuda_bf16.h>
#include <cstdint>

#define B_ 8
#define T_ 2048
#define C_ 1024
#define H_ 64
#define NROW (B_*T_)
#define PK 40   // proj smem k-stride (bf16)
#define PT 72   // flash smem stride (bf16)
#define NSPLIT 4

__device__ __nv_bfloat16 g_wh[192*C_];   // [n][k]
__device__ __nv_bfloat16 g_wl[192*C_];
__device__ __nv_bfloat16 g_qh[NROW*H_];
__device__ __nv_bfloat16 g_ql[NROW*H_];
__device__ __nv_bfloat16 g_kh[NROW*H_];
__device__ __nv_bfloat16 g_kl[NROW*H_];
__device__ __nv_bfloat16 g_vh[B_*H_*T_];   // [b][h][t]
__device__ __nv_bfloat16 g_vl[B_*H_*T_];

__device__ float g_Om[NSPLIT][NROW*H_];
__device__ float g_m[NSPLIT][NROW];
__device__ float g_l[NSPLIT][NROW];

// ---------------------------------------------------------------------------
__device__ __forceinline__ void mma_bf16(float* c, const uint32_t* a,
                                         uint32_t b0, uint32_t b1) {
    asm volatile("mma.sync.aligned.m16n8k16.row.col.f32.bf16.bf16.f32 "
        "{%0,%1,%2,%3}, {%4,%5,%6,%7}, {%8,%9}, {%0,%1,%2,%3};"
        : "+f"(c[0]), "+f"(c[1]), "+f"(c[2]), "+f"(c[3])
        : "r"(a[0]), "r"(a[1]), "r"(a[2]), "r"(a[3]), "r"(b0), "r"(b1));
}
__device__ __forceinline__ void split1(float v, __nv_bfloat16& h, __nv_bfloat16& l) {
    h = __float2bfloat16_rn(v);
    l = __float2bfloat16_rn(v - __bfloat162float(h));
}
__device__ __forceinline__ uint32_t packb(__nv_bfloat16 e0, __nv_bfloat16 e1) {
    return (uint32_t)__bfloat16_as_ushort(e0) |
           ((uint32_t)__bfloat16_as_ushort(e1) << 16);
}
__device__ __forceinline__ void split_pack(float a, float b, uint32_t& hi, uint32_t& lo) {
    __nv_bfloat16 ah, al, bh, bl;
    split1(a, ah, al); split1(b, bh, bl);
    hi = packb(ah, bh); lo = packb(al, bl);
}
__device__ __forceinline__ uint32_t s2u(const void* p) {
    uint32_t a;
    asm("{ .reg .u64 t; cvta.to.shared.u64 t, %1; cvt.u32.u64 %0, t; }" : "=r"(a) : "l"(p));
    return a;
}
__device__ __forceinline__ void cpa16(uint32_t dst, const void* src) {
    asm volatile("cp.async.cg.shared.global [%0], [%1], 16;" :: "r"(dst), "l"(src) : "memory");
}
#define CP_COMMIT() asm volatile("cp.async.commit_group;" ::: "memory")
#define CP_WAIT1()  asm volatile("cp.async.wait_group 1;" ::: "memory")
#define CP_WAIT0()  asm volatile("cp.async.wait_group 0;" ::: "memory")

// ---------------------------------------------------------------------------
// Kernel 0: split W into bf16 hi/lo, [n][k]. Block b handles n-row b.
// Coalesced 8B writes; reads are L2-resident.
// ---------------------------------------------------------------------------
__global__ __launch_bounds__(256) void wconv(
    const float* __restrict__ Wk, const float* __restrict__ Wq,
    const float* __restrict__ Wv)
{
    const int n = blockIdx.x;              // 0..191
    const int mat = n >> 6;                // 0=q,1=k,2=v
    const int col = n & 63;
    const int k4 = threadIdx.x * 4;        // 0..1020
    const float* W = (mat == 0) ? Wq : ((mat == 1) ? Wk : Wv);
    __nv_bfloat16 h[4], l[4];
#pragma unroll
    for (int j = 0; j < 4; j++)
        split1(W[(size_t)(k4 + j) * H_ + col], h[j], l[j]);
    uint2 ph = { packb(h[0], h[1]), packb(h[2], h[3]) };
    uint2 pl = { packb(l[0], l[1]), packb(l[2], l[3]) };
    *reinterpret_cast<uint2*>(&g_wh[(size_t)n * C_ + k4]) = ph;
    *reinterpret_cast<uint2*>(&g_wl[(size_t)n * C_ + k4]) = pl;
}

// ---------------------------------------------------------------------------
// Kernel 1: QKV projection (R6-proven version: scalar LDS fragments).
// ---------------------------------------------------------------------------
struct ProjS {
    __nv_bfloat16 xh[2][64*PK];
    __nv_bfloat16 xl[2][64*PK];
    __nv_bfloat16 wh[2][192*PK];
    __nv_bfloat16 wl[2][192*PK];
};

__global__ __launch_bounds__(256, 2) void qkv_proj(const float* __restrict__ x)
{
    extern __shared__ char smraw[];
    ProjS* sm = reinterpret_cast<ProjS*>(smraw);
    const int tid = threadIdx.x, lane = tid & 31, wid = tid >> 5;
    const int g = lane >> 2, tg = lane & 3;
    const int m0 = 32 * (wid >> 2);
    const int n0 = 48 * (wid & 3);
    const size_t rowBase = (size_t)blockIdx.x * 64;

    float acc[2][6][4];
#pragma unroll
    for (int a = 0; a < 2; a++)
#pragma unroll
        for (int b = 0; b < 6; b++)
#pragma unroll
            for (int c = 0; c < 4; c++) acc[a][b][c] = 0.0f;

#pragma unroll
    for (int i = 0; i < 3; i++) {
        int slot = tid + 256*i; int n = slot >> 2; int c8 = (slot & 3) * 8;
        cpa16(s2u(&sm->wh[0][n*PK + c8]), g_wh + (size_t)n * C_ + c8);
        cpa16(s2u(&sm->wl[0][n*PK + c8]), g_wl + (size_t)n * C_ + c8);
    }
    CP_COMMIT();
    float4 xr[2];
#pragma unroll
    for (int i = 0; i < 2; i++) {
        int slot = tid + 256*i; int r = slot >> 3; int c = (slot & 7) * 4;
        xr[i] = *(const float4*)(x + (rowBase + r) * C_ + c);
    }

    for (int it = 0; it < 32; ++it) {
        const int s = it & 1;
#pragma unroll
        for (int i = 0; i < 2; i++) {
            int slot = tid + 256*i; int r = slot >> 3; int c = (slot & 7) * 4;
            uint32_t h0, l0, h1, l1;
            split_pack(xr[i].x, xr[i].y, h0, l0);
            split_pack(xr[i].z, xr[i].w, h1, l1);
            uint2 ph = { h0, h1 }, pl = { l0, l1 };
            *reinterpret_cast<uint2*>(&sm->xh[s][r*PK + c]) = ph;
            *reinterpret_cast<uint2*>(&sm->xl[s][r*PK + c]) = pl;
        }
        if (it < 31) {
            const int kt = (it + 1) * 32;
#pragma unroll
            for (int i = 0; i < 3; i++) {
                int slot = tid + 256*i; int n = slot >> 2; int c8 = (slot & 3) * 8;
                cpa16(s2u(&sm->wh[1-s][n*PK + c8]), g_wh + (size_t)n * C_ + kt + c8);
                cpa16(s2u(&sm->wl[1-s][n*PK + c8]), g_wl + (size_t)n * C_ + kt + c8);
            }
        }
        CP_COMMIT();
        CP_WAIT1();
        __syncthreads();

        if (it < 31) {
            const int kt = (it + 1) * 32;
#pragma unroll
            for (int i = 0; i < 2; i++) {
                int slot = tid + 256*i; int r = slot >> 3; int c = (slot & 7) * 4;
                xr[i] = *(const float4*)(x + (rowBase + r) * C_ + kt + c);
            }
        }

        const uint32_t* xhp = reinterpret_cast<const uint32_t*>(sm->xh[s]);
        const uint32_t* xlp = reinterpret_cast<const uint32_t*>(sm->xl[s]);
        const uint32_t* whp = reinterpret_cast<const uint32_t*>(sm->wh[s]);
        const uint32_t* wlp = reinterpret_cast<const uint32_t*>(sm->wl[s]);
#pragma unroll
        for (int ks = 0; ks < 2; ks++) {
            const int kw = tg + 8*ks;
            uint32_t ah[2][4], al[2][4];
#pragma unroll
            for (int mt = 0; mt < 2; mt++) {
                int r = m0 + 16*mt + g;
                ah[mt][0] = xhp[r*20 + kw];      ah[mt][1] = xhp[(r+8)*20 + kw];
                ah[mt][2] = xhp[r*20 + kw + 4];  ah[mt][3] = xhp[(r+8)*20 + kw + 4];
                al[mt][0] = xlp[r*20 + kw];      al[mt][1] = xlp[(r+8)*20 + kw];
                al[mt][2] = xlp[r*20 + kw + 4];  al[mt][3] = xlp[(r+8)*20 + kw + 4];
            }
#pragma unroll
            for (int nt = 0; nt < 6; nt++) {
                int n = n0 + 8*nt + g;
                uint32_t bh0 = whp[n*20 + kw], bh1 = whp[n*20 + kw + 4];
                uint32_t bl0 = wlp[n*20 + kw], bl1 = wlp[n*20 + kw + 4];
#pragma unroll
                for (int mt = 0; mt < 2; mt++) {
                    mma_bf16(acc[mt][nt], ah[mt], bh0, bh1);
                    mma_bf16(acc[mt][nt], ah[mt], bl0, bl1);
                    mma_bf16(acc[mt][nt], al[mt], bh0, bh1);
                }
            }
        }
        __syncthreads();
    }

    const float qscale = 0.03125f;
#pragma unroll
    for (int mt = 0; mt < 2; mt++) {
#pragma unroll
        for (int nt = 0; nt < 6; nt++) {
            int gc = n0 + 8*nt;
            float* c = acc[mt][nt];
            int r0 = m0 + 16*mt + g;
            size_t row0 = rowBase + r0, row1 = row0 + 8;
            if (gc < 64) {
                int col = gc + 2*tg;
                uint32_t h, l;
                split_pack(c[0]*qscale, c[1]*qscale, h, l);
                *reinterpret_cast<uint32_t*>(&g_qh[row0*H_ + col]) = h;
                *reinterpret_cast<uint32_t*>(&g_ql[row0*H_ + col]) = l;
                split_pack(c[2]*qscale, c[3]*qscale, h, l);
                *reinterpret_cast<uint32_t*>(&g_qh[row1*H_ + col]) = h;
                *reinterpret_cast<uint32_t*>(&g_ql[row1*H_ + col]) = l;
            } else if (gc < 128) {
                int col = gc - 64 + 2*tg;
                uint32_t h, l;
                split_pack(c[0], c[1], h, l);
                *reinterpret_cast<uint32_t*>(&g_kh[row0*H_ + col]) = h;
                *reinterpret_cast<uint32_t*>(&g_kl[row0*H_ + col]) = l;
                split_pack(c[2], c[3], h, l);
                *reinterpret_cast<uint32_t*>(&g_kh[row1*H_ + col]) = h;
                *reinterpret_cast<uint32_t*>(&g_kl[row1*H_ + col]) = l;
            } else {
                int h0 = gc - 128 + 2*tg;
                size_t bb = rowBase >> 11;
                size_t tb = (rowBase & 2047);
                __nv_bfloat16 hh, ll;
                split1(c[0], hh, ll);
                g_vh[(bb*H_ + h0    )*T_ + tb + r0] = hh;
                g_vl[(bb*H_ + h0    )*T_ + tb + r0] = ll;
                split1(c[1], hh, ll);
                g_vh[(bb*H_ + h0 + 1)*T_ + tb + r0] = hh;
                g_vl[(bb*H_ + h0 + 1)*T_ + tb + r0] = ll;
                split1(c[2], hh, ll);
                g_vh[(bb*H_ + h0    )*T_ + tb + r0 + 8] = hh;
                g_vl[(bb*H_ + h0    )*T_ + tb + r0 + 8] = ll;
                split1(c[3], hh, ll);
                g_vh[(bb*H_ + h0 + 1)*T_ + tb + r0 + 8] = hh;
                g_vl[(bb*H_ + h0 + 1)*T_ + tb + r0 + 8] = ll;
            }
        }
    }
}

// ---------------------------------------------------------------------------
// Kernel 2: 4-way split-KV causal flash attention (R6 body, parity mod 4).
// ---------------------------------------------------------------------------
struct FaS {
    __nv_bfloat16 qh[64*PT], ql[64*PT];
    __nv_bfloat16 kh[2][64*PT], kl[2][64*PT];
    __nv_bfloat16 vh[2][64*PT], vl[2][64*PT];
};

__global__ __launch_bounds__(128) void flash_mma()
{
    extern __shared__ char smraw[];
    FaS* sm = reinterpret_cast<FaS*>(smraw);
    const int tid = threadIdx.x, lane = tid & 31;
    const int g = lane >> 2, tg = lane & 3;
    const int m0 = 16 * (tid >> 5);
    const int blk = blockIdx.x;
    const int h    = blk & (NSPLIT - 1);
    const int rest = blk >> 2;
    const int qt = 31 - (rest >> 3);   // heavy tiles first
    const int b  = rest & 7;
    const int ntiles = (qt >= h) ? ((qt - h) >> 2) + 1 : 0;

    const __nv_bfloat16* khb = g_kh + (size_t)b*T_*H_;
    const __nv_bfloat16* klb = g_kl + (size_t)b*T_*H_;
    const __nv_bfloat16* vhb = g_vh + (size_t)b*H_*T_;
    const __nv_bfloat16* vlb = g_vl + (size_t)b*H_*T_;

    {
        const __nv_bfloat16* sh = g_qh + (size_t)(b*T_ + qt*64) * H_;
        const __nv_bfloat16* sl = g_ql + (size_t)(b*T_ + qt*64) * H_;
        const int t0 = h * 64;
#pragma unroll
        for (int i = 0; i < 4; i++) {
            int slot = tid + 128*i; int r = slot >> 3; int c = (slot & 7) * 8;
            cpa16(s2u(&sm->qh[r*PT + c]), sh + r*H_ + c);
            cpa16(s2u(&sm->ql[r*PT + c]), sl + r*H_ + c);
            if (ntiles > 0) {
                cpa16(s2u(&sm->kh[0][r*PT + c]), khb + (size_t)(t0 + r)*H_ + c);
                cpa16(s2u(&sm->kl[0][r*PT + c]), klb + (size_t)(t0 + r)*H_ + c);
                cpa16(s2u(&sm->vh[0][r*PT + c]), vhb + (size_t)r*T_ + t0 + c);
                cpa16(s2u(&sm->vl[0][r*PT + c]), vlb + (size_t)r*T_ + t0 + c);
            }
        }
        CP_COMMIT();
    }

    float O[8][4];
#pragma unroll
    for (int a = 0; a < 8; a++)
#pragma unroll
        for (int c = 0; c < 4; c++) O[a][c] = 0.0f;
    float mr[2] = { -1e30f, -1e30f }, lr[2] = { 0.0f, 0.0f };

    for (int i = 0; i < ntiles; ++i) {
        const int kvt = h + NSPLIT*i;
        const int s = i & 1;
        __syncthreads();
        if (i + 1 < ntiles) {
            const int nt4 = (kvt + NSPLIT) * 64;
#pragma unroll
            for (int j = 0; j < 4; j++) {
                int slot = tid + 128*j; int r = slot >> 3; int c = (slot & 7) * 8;
                cpa16(s2u(&sm->kh[1-s][r*PT + c]), khb + (size_t)(nt4 + r)*H_ + c);
                cpa16(s2u(&sm->kl[1-s][r*PT + c]), klb + (size_t)(nt4 + r)*H_ + c);
                cpa16(s2u(&sm->vh[1-s][r*PT + c]), vhb + (size_t)r*T_ + nt4 + c);
                cpa16(s2u(&sm->vl[1-s][r*PT + c]), vlb + (size_t)r*T_ + nt4 + c);
            }
        }
        CP_COMMIT();
        CP_WAIT1();
        __syncthreads();

        float Sf[8][4];
#pragma unroll
        for (int a = 0; a < 8; a++)
#pragma unroll
            for (int c = 0; c < 4; c++) Sf[a][c] = 0.0f;

        const uint32_t* qhp = reinterpret_cast<const uint32_t*>(sm->qh);
        const uint32_t* qlp = reinterpret_cast<const uint32_t*>(sm->ql);
        const uint32_t* khp = reinterpret_cast<const uint32_t*>(sm->kh[s]);
        const uint32_t* klp = reinterpret_cast<const uint32_t*>(sm->kl[s]);
#pragma unroll
        for (int ks = 0; ks < 4; ks++) {
            const int kw = tg + 8*ks;
            uint32_t ah[4], al[4];
            int r = m0 + g;
            ah[0] = qhp[r*36 + kw];       ah[1] = qhp[(r+8)*36 + kw];
            ah[2] = qhp[r*36 + kw + 4];   ah[3] = qhp[(r+8)*36 + kw + 4];
            al[0] = qlp[r*36 + kw];       al[1] = qlp[(r+8)*36 + kw];
            al[2] = qlp[r*36 + kw + 4];   al[3] = qlp[(r+8)*36 + kw + 4];
#pragma unroll
            for (int nt = 0; nt < 8; nt++) {
                int n = 8*nt + g;
                uint32_t bh0 = khp[n*36 + kw], bh1 = khp[n*36 + kw + 4];
                uint32_t bl0 = klp[n*36 + kw], bl1 = klp[n*36 + kw + 4];
                mma_bf16(Sf[nt], ah, bh0, bh1);
                mma_bf16(Sf[nt], ah, bl0, bl1);
                mma_bf16(Sf[nt], al, bh0, bh1);
            }
        }

        if (kvt == qt) {
#pragma unroll
            for (int nt = 0; nt < 8; nt++) {
                int colb = 8*nt + 2*tg;
                int row0 = m0 + g, row1 = row0 + 8;
                if (colb     > row0) Sf[nt][0] = -1e30f;
                if (colb + 1 > row0) Sf[nt][1] = -1e30f;
                if (colb     > row1) Sf[nt][2] = -1e30f;
                if (colb + 1 > row1) Sf[nt][3] = -1e30f;
            }
        }

#pragma unroll
        for (int rr = 0; rr < 2; rr++) {
            float mx = -1e30f;
#pragma unroll
            for (int nt = 0; nt < 8; nt++)
                mx = fmaxf(mx, fmaxf(Sf[nt][2*rr], Sf[nt][2*rr+1]));
            mx = fmaxf(mx, __shfl_xor_sync(0xffffffffu, mx, 1));
            mx = fmaxf(mx, __shfl_xor_sync(0xffffffffu, mx, 2));
            float mn = fmaxf(mr[rr], mx);
            float corr = __expf(mr[rr] - mn);
            mr[rr] = mn;
            float sum = 0.0f;
#pragma unroll
            for (int nt = 0; nt < 8; nt++) {
                float p0 = __expf(Sf[nt][2*rr]   - mn);
                float p1 = __expf(Sf[nt][2*rr+1] - mn);
                Sf[nt][2*rr] = p0; Sf[nt][2*rr+1] = p1;
                sum += p0 + p1;
            }
            sum += __shfl_xor_sync(0xffffffffu, sum, 1);
            sum += __shfl_xor_sync(0xffffffffu, sum, 2);
            lr[rr] = lr[rr]*corr + sum;
#pragma unroll
            for (int nt = 0; nt < 8; nt++) {
                O[nt][2*rr]   *= corr;
                O[nt][2*rr+1] *= corr;
            }
        }

        const uint32_t* vhp = reinterpret_cast<const uint32_t*>(sm->vh[s]);
        const uint32_t* vlp = reinterpret_cast<const uint32_t*>(sm->vl[s]);
#pragma unroll
        for (int ks = 0; ks < 4; ks++) {
            uint32_t ph[4], pl[4];
            split_pack(Sf[2*ks][0],   Sf[2*ks][1],   ph[0], pl[0]);
            split_pack(Sf[2*ks][2],   Sf[2*ks][3],   ph[1], pl[1]);
            split_pack(Sf[2*ks+1][0], Sf[2*ks+1][1], ph[2], pl[2]);
            split_pack(Sf[2*ks+1][2], Sf[2*ks+1][3], ph[3], pl[3]);
            const int kw = tg + 8*ks;
#pragma unroll
            for (int nt = 0; nt < 8; nt++) {
                int n = 8*nt + g;
                uint32_t bh0 = vhp[n*36 + kw], bh1 = vhp[n*36 + kw + 4];
                uint32_t bl0 = vlp[n*36 + kw], bl1 = vlp[n*36 + kw + 4];
                mma_bf16(O[nt], ph, bh0, bh1);
                mma_bf16(O[nt], ph, bl0, bl1);
                mma_bf16(O[nt], pl, bh0, bh1);
            }
        }
    }

    CP_WAIT0();

    size_t row0 = (size_t)b*T_ + (size_t)qt*64 + m0 + g;
    size_t row1 = row0 + 8;
    float* Od = g_Om[h];
#pragma unroll
    for (int nt = 0; nt < 8; nt++) {
        int col = 8*nt + 2*tg;
        float2 v0 = { O[nt][0], O[nt][1] };
        float2 v1 = { O[nt][2], O[nt][3] };
        *reinterpret_cast<float2*>(Od + row0*H_ + col) = v0;
        *reinterpret_cast<float2*>(Od + row1*H_ + col) = v1;
    }
    if (tg == 0) {
        g_m[h][row0] = mr[0]; g_l[h][row0] = lr[0];
        g_m[h][row1] = mr[1]; g_l[h][row1] = lr[1];
    }
}

// ---------------------------------------------------------------------------
// Kernel 3: merge the NSPLIT partials.
// ---------------------------------------------------------------------------
__global__ __launch_bounds__(256) void fa_merge(float* __restrict__ out)
{
    int idx = blockIdx.x * 256 + threadIdx.x;
    int row = idx >> 4;
    int c4  = (idx & 15) * 4;
    float mv[NSPLIT], lv[NSPLIT];
    float M = -1e30f;
#pragma unroll
    for (int hh = 0; hh < NSPLIT; hh++) {
        mv[hh] = g_m[hh][row];
        lv[hh] = g_l[hh][row];
        M = fmaxf(M, mv[hh]);
    }
    float denom = 0.0f;
    float a[NSPLIT];
#pragma unroll
    for (int hh = 0; hh < NSPLIT; hh++) {
        a[hh] = __expf(mv[hh] - M);
        denom += lv[hh] * a[hh];
    }
    float inv = 1.0f / denom;
    float4 r = { 0.0f, 0.0f, 0.0f, 0.0f };
#pragma unroll
    for (int hh = 0; hh < NSPLIT; hh++) {
        float4 o = *reinterpret_cast<const float4*>(&g_Om[hh][(size_t)row*H_ + c4]);
        r.x += o.x * a[hh];
        r.y += o.y * a[hh];
        r.z += o.z * a[hh];
        r.w += o.w * a[hh];
    }
    r.x *= inv; r.y *= inv; r.z *= inv; r.w *= inv;
    *reinterpret_cast<float4*>(out + (size_t)row*H_ + c4) = r;
}

// ---------------------------------------------------------------------------
extern "C" void kernel_launch(void* const* d_in, const int* in_sizes, int n_in,
                              void* d_out, int out_size)
{
    const float* x  = (const float*)d_in[0];
    const float* Wk = (const float*)d_in[1];
    const float* Wq = (const float*)d_in[2];
    const float* Wv = (const float*)d_in[3];
    float* out = (float*)d_out;

    wconv<<<192, 256>>>(Wk, Wq, Wv);

    const int psm = (int)sizeof(ProjS);   // 81920
    cudaFuncSetAttribute(qkv_proj, cudaFuncAttributeMaxDynamicSharedMemorySize, psm);
    qkv_proj<<<NROW / 64, 256, psm>>>(x);

    const int fsm = (int)sizeof(FaS);     // 92160
    cudaFuncSetAttribute(flash_mma, cudaFuncAttributeMaxDynamicSharedMemorySize, fsm);
    flash_mma<<<(T_/64) * B_ * NSPLIT, 128, fsm>>>();

    fa_merge<<<NROW * H_ / 4 / 256, 256>>>(out);
}

// round 9
// speedup vs baseline: 1.7826x; 1.7357x over previous
#include <cuda_runtime.h>
#include <cuda_fp16.h>
#include <cstdint>

#define B_ 8
#define T_ 2048
#define C_ 1024
#define H_ 64
#define NROW (B_*T_)
#define PK 40   // proj smem k-stride (fp16)
#define PT 72   // flash smem stride (fp16)
#define NSPLIT 2

__device__ __half g_w[192*C_];    // [n][k], n: 0-63 q, 64-127 k, 128-191 v
__device__ __half g_q[NROW*H_];   // pre-scaled by C^-0.5
__device__ __half g_k[NROW*H_];
__device__ __half g_v[B_*H_*T_];  // [b][h][t]

__device__ float g_Om[NSPLIT][NROW*H_];
__device__ float g_m[NSPLIT][NROW];
__device__ float g_l[NSPLIT][NROW];

// ---------------------------------------------------------------------------
__device__ __forceinline__ void mma_f16(float* c, const uint32_t* a,
                                        uint32_t b0, uint32_t b1) {
    asm volatile("mma.sync.aligned.m16n8k16.row.col.f32.f16.f16.f32 "
        "{%0,%1,%2,%3}, {%4,%5,%6,%7}, {%8,%9}, {%0,%1,%2,%3};"
        : "+f"(c[0]), "+f"(c[1]), "+f"(c[2]), "+f"(c[3])
        : "r"(a[0]), "r"(a[1]), "r"(a[2]), "r"(a[3]), "r"(b0), "r"(b1));
}
__device__ __forceinline__ uint32_t pack2h(float a, float b) {
    __half2 h = __floats2half2_rn(a, b);
    return *reinterpret_cast<uint32_t*>(&h);
}
__device__ __forceinline__ uint32_t s2u(const void* p) {
    uint32_t a;
    asm("{ .reg .u64 t; cvta.to.shared.u64 t, %1; cvt.u32.u64 %0, t; }" : "=r"(a) : "l"(p));
    return a;
}
__device__ __forceinline__ void cpa16(uint32_t dst, const void* src) {
    asm volatile("cp.async.cg.shared.global [%0], [%1], 16;" :: "r"(dst), "l"(src) : "memory");
}
#define CP_COMMIT() asm volatile("cp.async.commit_group;" ::: "memory")
#define CP_WAIT1()  asm volatile("cp.async.wait_group 1;" ::: "memory")
#define CP_WAIT0()  asm volatile("cp.async.wait_group 0;" ::: "memory")

// ---------------------------------------------------------------------------
// Kernel 0: convert W to fp16, transposed to [n][k]. Block n, coalesced 8B writes.
// ---------------------------------------------------------------------------
__global__ __launch_bounds__(256) void wconv(
    const float* __restrict__ Wk, const float* __restrict__ Wq,
    const float* __restrict__ Wv)
{
    const int n = blockIdx.x;              // 0..191
    const int mat = n >> 6;                // 0=q,1=k,2=v
    const int col = n & 63;
    const int k4 = threadIdx.x * 4;
    const float* W = (mat == 0) ? Wq : ((mat == 1) ? Wk : Wv);
    float f[4];
#pragma unroll
    for (int j = 0; j < 4; j++) f[j] = W[(size_t)(k4 + j) * H_ + col];
    uint2 p = { pack2h(f[0], f[1]), pack2h(f[2], f[3]) };
    *reinterpret_cast<uint2*>(&g_w[(size_t)n * C_ + k4]) = p;
}

// ---------------------------------------------------------------------------
// Kernel 1: QKV projection, fp16 single-pass mma.
// Block: 256 thr (8 warps = 2M x 4N), M-tile 64, N=192, K chunks 32.
// ---------------------------------------------------------------------------
struct ProjS {
    __half xs[2][64*PK];
    __half ws[2][192*PK];
};

__global__ __launch_bounds__(256, 2) void qkv_proj(const float* __restrict__ x)
{
    extern __shared__ char smraw[];
    ProjS* sm = reinterpret_cast<ProjS*>(smraw);
    const int tid = threadIdx.x, lane = tid & 31, wid = tid >> 5;
    const int g = lane >> 2, tg = lane & 3;
    const int m0 = 32 * (wid >> 2);
    const int n0 = 48 * (wid & 3);
    const size_t rowBase = (size_t)blockIdx.x * 64;

    float acc[2][6][4];
#pragma unroll
    for (int a = 0; a < 2; a++)
#pragma unroll
        for (int b = 0; b < 6; b++)
#pragma unroll
            for (int c = 0; c < 4; c++) acc[a][b][c] = 0.0f;

    // prologue: W0 via cp.async (3 cpa/thread), x0 via fp32 reg prefetch
#pragma unroll
    for (int i = 0; i < 3; i++) {
        int slot = tid + 256*i; int n = slot >> 2; int c8 = (slot & 3) * 8;
        cpa16(s2u(&sm->ws[0][n*PK + c8]), g_w + (size_t)n * C_ + c8);
    }
    CP_COMMIT();
    float4 xr[2];
#pragma unroll
    for (int i = 0; i < 2; i++) {
        int slot = tid + 256*i; int r = slot >> 3; int c = (slot & 7) * 4;
        xr[i] = *(const float4*)(x + (rowBase + r) * C_ + c);
    }

    for (int it = 0; it < 32; ++it) {
        const int s = it & 1;
        // convert + store staged x into stage s
#pragma unroll
        for (int i = 0; i < 2; i++) {
            int slot = tid + 256*i; int r = slot >> 3; int c = (slot & 7) * 4;
            uint2 p = { pack2h(xr[i].x, xr[i].y), pack2h(xr[i].z, xr[i].w) };
            *reinterpret_cast<uint2*>(&sm->xs[s][r*PK + c]) = p;
        }
        if (it < 31) {
            const int kt = (it + 1) * 32;
#pragma unroll
            for (int i = 0; i < 3; i++) {
                int slot = tid + 256*i; int n = slot >> 2; int c8 = (slot & 3) * 8;
                cpa16(s2u(&sm->ws[1-s][n*PK + c8]), g_w + (size_t)n * C_ + kt + c8);
            }
        }
        CP_COMMIT();
        CP_WAIT1();
        __syncthreads();

        if (it < 31) {
            const int kt = (it + 1) * 32;
#pragma unroll
            for (int i = 0; i < 2; i++) {
                int slot = tid + 256*i; int r = slot >> 3; int c = (slot & 7) * 4;
                xr[i] = *(const float4*)(x + (rowBase + r) * C_ + kt + c);
            }
        }

        const uint32_t* xp = reinterpret_cast<const uint32_t*>(sm->xs[s]);
        const uint32_t* wp = reinterpret_cast<const uint32_t*>(sm->ws[s]);
#pragma unroll
        for (int ks = 0; ks < 2; ks++) {
            const int kw = tg + 8*ks;
            uint32_t ah[2][4];
#pragma unroll
            for (int mt = 0; mt < 2; mt++) {
                int r = m0 + 16*mt + g;
                ah[mt][0] = xp[r*20 + kw];      ah[mt][1] = xp[(r+8)*20 + kw];
                ah[mt][2] = xp[r*20 + kw + 4];  ah[mt][3] = xp[(r+8)*20 + kw + 4];
            }
#pragma unroll
            for (int nt = 0; nt < 6; nt++) {
                int n = n0 + 8*nt + g;
                uint32_t b0 = wp[n*20 + kw], b1 = wp[n*20 + kw + 4];
#pragma unroll
                for (int mt = 0; mt < 2; mt++)
                    mma_f16(acc[mt][nt], ah[mt], b0, b1);
            }
        }
        __syncthreads();
    }

    const float qscale = 0.03125f;   // C^-0.5
#pragma unroll
    for (int mt = 0; mt < 2; mt++) {
#pragma unroll
        for (int nt = 0; nt < 6; nt++) {
            int gc = n0 + 8*nt;
            float* c = acc[mt][nt];
            int r0 = m0 + 16*mt + g;
            size_t row0 = rowBase + r0, row1 = row0 + 8;
            if (gc < 64) {
                int col = gc + 2*tg;
                *reinterpret_cast<uint32_t*>(&g_q[row0*H_ + col]) = pack2h(c[0]*qscale, c[1]*qscale);
                *reinterpret_cast<uint32_t*>(&g_q[row1*H_ + col]) = pack2h(c[2]*qscale, c[3]*qscale);
            } else if (gc < 128) {
                int col = gc - 64 + 2*tg;
                *reinterpret_cast<uint32_t*>(&g_k[row0*H_ + col]) = pack2h(c[0], c[1]);
                *reinterpret_cast<uint32_t*>(&g_k[row1*H_ + col]) = pack2h(c[2], c[3]);
            } else {
                int h0 = gc - 128 + 2*tg;
                size_t bb = rowBase >> 11;
                size_t tb = (rowBase & 2047);
                g_v[(bb*H_ + h0    )*T_ + tb + r0]     = __float2half_rn(c[0]);
                g_v[(bb*H_ + h0 + 1)*T_ + tb + r0]     = __float2half_rn(c[1]);
                g_v[(bb*H_ + h0    )*T_ + tb + r0 + 8] = __float2half_rn(c[2]);
                g_v[(bb*H_ + h0 + 1)*T_ + tb + r0 + 8] = __float2half_rn(c[3]);
            }
        }
    }
}

// ---------------------------------------------------------------------------
// Kernel 2: 2-way split-KV causal flash attention, fp16 single-pass mma.
// ---------------------------------------------------------------------------
struct FaS {
    __half qh[64*PT];
    __half kh[2][64*PT];
    __half vh[2][64*PT];   // [h][t]
};

__global__ __launch_bounds__(128, 4) void flash_mma()
{
    extern __shared__ char smraw[];
    FaS* sm = reinterpret_cast<FaS*>(smraw);
    const int tid = threadIdx.x, lane = tid & 31;
    const int g = lane >> 2, tg = lane & 3;
    const int m0 = 16 * (tid >> 5);
    const int blk = blockIdx.x;
    const int h    = blk & 1;
    const int rest = blk >> 1;
    const int qt = 31 - (rest >> 3);   // heavy tiles first
    const int b  = rest & 7;
    const int ntiles = (qt >= h) ? ((qt - h) >> 1) + 1 : 0;

    const __half* khb = g_k + (size_t)b*T_*H_;
    const __half* vhb = g_v + (size_t)b*H_*T_;

    // prologue: Q (+ first KV tile if any)
    {
        const __half* sh = g_q + (size_t)(b*T_ + qt*64) * H_;
        const int t0 = h * 64;
#pragma unroll
        for (int i = 0; i < 4; i++) {
            int slot = tid + 128*i; int r = slot >> 3; int c = (slot & 7) * 8;
            cpa16(s2u(&sm->qh[r*PT + c]), sh + r*H_ + c);
            if (ntiles > 0) {
                cpa16(s2u(&sm->kh[0][r*PT + c]), khb + (size_t)(t0 + r)*H_ + c);
                cpa16(s2u(&sm->vh[0][r*PT + c]), vhb + (size_t)r*T_ + t0 + c);
            }
        }
        CP_COMMIT();
    }

    float O[8][4];
#pragma unroll
    for (int a = 0; a < 8; a++)
#pragma unroll
        for (int c = 0; c < 4; c++) O[a][c] = 0.0f;
    float mr[2] = { -1e30f, -1e30f }, lr[2] = { 0.0f, 0.0f };

    for (int i = 0; i < ntiles; ++i) {
        const int kvt = h + 2*i;
        const int s = i & 1;
        __syncthreads();
        if (i + 1 < ntiles) {
            const int nt4 = (kvt + 2) * 64;
#pragma unroll
            for (int j = 0; j < 4; j++) {
                int slot = tid + 128*j; int r = slot >> 3; int c = (slot & 7) * 8;
                cpa16(s2u(&sm->kh[1-s][r*PT + c]), khb + (size_t)(nt4 + r)*H_ + c);
                cpa16(s2u(&sm->vh[1-s][r*PT + c]), vhb + (size_t)r*T_ + nt4 + c);
            }
        }
        CP_COMMIT();
        CP_WAIT1();
        __syncthreads();

        float Sf[8][4];
#pragma unroll
        for (int a = 0; a < 8; a++)
#pragma unroll
            for (int c = 0; c < 4; c++) Sf[a][c] = 0.0f;

        const uint32_t* qp = reinterpret_cast<const uint32_t*>(sm->qh);
        const uint32_t* kp = reinterpret_cast<const uint32_t*>(sm->kh[s]);
#pragma unroll
        for (int ks = 0; ks < 4; ks++) {
            const int kw = tg + 8*ks;
            uint32_t ah[4];
            int r = m0 + g;
            ah[0] = qp[r*36 + kw];       ah[1] = qp[(r+8)*36 + kw];
            ah[2] = qp[r*36 + kw + 4];   ah[3] = qp[(r+8)*36 + kw + 4];
#pragma unroll
            for (int nt = 0; nt < 8; nt++) {
                int n = 8*nt + g;
                mma_f16(Sf[nt], ah, kp[n*36 + kw], kp[n*36 + kw + 4]);
            }
        }

        if (kvt == qt) {
#pragma unroll
            for (int nt = 0; nt < 8; nt++) {
                int colb = 8*nt + 2*tg;
                int row0 = m0 + g, row1 = row0 + 8;
                if (colb     > row0) Sf[nt][0] = -1e30f;
                if (colb + 1 > row0) Sf[nt][1] = -1e30f;
                if (colb     > row1) Sf[nt][2] = -1e30f;
                if (colb + 1 > row1) Sf[nt][3] = -1e30f;
            }
        }

#pragma unroll
        for (int rr = 0; rr < 2; rr++) {
            float mx = -1e30f;
#pragma unroll
            for (int nt = 0; nt < 8; nt++)
                mx = fmaxf(mx, fmaxf(Sf[nt][2*rr], Sf[nt][2*rr+1]));
            mx = fmaxf(mx, __shfl_xor_sync(0xffffffffu, mx, 1));
            mx = fmaxf(mx, __shfl_xor_sync(0xffffffffu, mx, 2));
            float mn = fmaxf(mr[rr], mx);
            float corr = __expf(mr[rr] - mn);
            mr[rr] = mn;
            float sum = 0.0f;
#pragma unroll
            for (int nt = 0; nt < 8; nt++) {
                float p0 = __expf(Sf[nt][2*rr]   - mn);
                float p1 = __expf(Sf[nt][2*rr+1] - mn);
                Sf[nt][2*rr] = p0; Sf[nt][2*rr+1] = p1;
                sum += p0 + p1;
            }
            sum += __shfl_xor_sync(0xffffffffu, sum, 1);
            sum += __shfl_xor_sync(0xffffffffu, sum, 2);
            lr[rr] = lr[rr]*corr + sum;
#pragma unroll
            for (int nt = 0; nt < 8; nt++) {
                O[nt][2*rr]   *= corr;
                O[nt][2*rr+1] *= corr;
            }
        }

        const uint32_t* vp = reinterpret_cast<const uint32_t*>(sm->vh[s]);
#pragma unroll
        for (int ks = 0; ks < 4; ks++) {
            uint32_t ph[4];
            ph[0] = pack2h(Sf[2*ks][0],   Sf[2*ks][1]);
            ph[1] = pack2h(Sf[2*ks][2],   Sf[2*ks][3]);
            ph[2] = pack2h(Sf[2*ks+1][0], Sf[2*ks+1][1]);
            ph[3] = pack2h(Sf[2*ks+1][2], Sf[2*ks+1][3]);
            const int kw = tg + 8*ks;
#pragma unroll
            for (int nt = 0; nt < 8; nt++) {
                int n = 8*nt + g;
                mma_f16(O[nt], ph, vp[n*36 + kw], vp[n*36 + kw + 4]);
            }
        }
    }

    CP_WAIT0();

    size_t row0 = (size_t)b*T_ + (size_t)qt*64 + m0 + g;
    size_t row1 = row0 + 8;
    float* Od = g_Om[h];
#pragma unroll
    for (int nt = 0; nt < 8; nt++) {
        int col = 8*nt + 2*tg;
        float2 v0 = { O[nt][0], O[nt][1] };
        float2 v1 = { O[nt][2], O[nt][3] };
        *reinterpret_cast<float2*>(Od + row0*H_ + col) = v0;
        *reinterpret_cast<float2*>(Od + row1*H_ + col) = v1;
    }
    if (tg == 0) {
        g_m[h][row0] = mr[0]; g_l[h][row0] = lr[0];
        g_m[h][row1] = mr[1]; g_l[h][row1] = lr[1];
    }
}

// ---------------------------------------------------------------------------
// Kernel 3: merge the two split-KV partials.
// ---------------------------------------------------------------------------
__global__ __launch_bounds__(256) void fa_merge(float* __restrict__ out)
{
    int idx = blockIdx.x * 256 + threadIdx.x;
    int row = idx >> 4;
    int c4  = (idx & 15) * 4;
    float m0v = g_m[0][row], m1v = g_m[1][row];
    float l0v = g_l[0][row], l1v = g_l[1][row];
    float M = fmaxf(m0v, m1v);
    float a0 = __expf(m0v - M), a1 = __expf(m1v - M);
    float inv = 1.0f / (l0v * a0 + l1v * a1);
    float4 o0 = *reinterpret_cast<const float4*>(&g_Om[0][(size_t)row*H_ + c4]);
    float4 o1 = *reinterpret_cast<const float4*>(&g_Om[1][(size_t)row*H_ + c4]);
    float4 r;
    r.x = (o0.x*a0 + o1.x*a1) * inv;
    r.y = (o0.y*a0 + o1.y*a1) * inv;
    r.z = (o0.z*a0 + o1.z*a1) * inv;
    r.w = (o0.w*a0 + o1.w*a1) * inv;
    *reinterpret_cast<float4*>(out + (size_t)row*H_ + c4) = r;
}

// ---------------------------------------------------------------------------
extern "C" void kernel_launch(void* const* d_in, const int* in_sizes, int n_in,
                              void* d_out, int out_size)
{
    const float* x  = (const float*)d_in[0];
    const float* Wk = (const float*)d_in[1];
    const float* Wq = (const float*)d_in[2];
    const float* Wv = (const float*)d_in[3];
    float* out = (float*)d_out;

    wconv<<<192, 256>>>(Wk, Wq, Wv);

    const int psm = (int)sizeof(ProjS);   // 40960
    cudaFuncSetAttribute(qkv_proj, cudaFuncAttributeMaxDynamicSharedMemorySize, psm);
    qkv_proj<<<NROW / 64, 256, psm>>>(x);

    const int fsm = (int)sizeof(FaS);     // 46080
    cudaFuncSetAttribute(flash_mma, cudaFuncAttributeMaxDynamicSharedMemorySize, fsm);
    flash_mma<<<(T_/64) * B_ * NSPLIT, 128, fsm>>>();

    fa_merge<<<NROW * H_ / 4 / 256, 256>>>(out);
}

// round 10
// speedup vs baseline: 1.7881x; 1.0031x over previous
#include <cuda_runtime.h>
#include <cuda_fp16.h>
#include <cstdint>

#define B_ 8
#define T_ 2048
#define C_ 1024
#define H_ 64
#define NROW (B_*T_)
#define PK 40   // proj smem k-stride (fp16)
#define PT 72   // flash smem stride (fp16)
#define NSPLIT 2

__device__ __half g_w[192*C_];    // [n][k]
__device__ __half g_q[NROW*H_];   // pre-scaled by C^-0.5
__device__ __half g_k[NROW*H_];
__device__ __half g_v[B_*H_*T_];  // [b][h][t]

__device__ float g_Om[NSPLIT][NROW*H_];
__device__ float g_m[NSPLIT][NROW];
__device__ float g_l[NSPLIT][NROW];

// ---------------------------------------------------------------------------
__device__ __forceinline__ void mma_f16(float* c, const uint32_t* a,
                                        uint32_t b0, uint32_t b1) {
    asm volatile("mma.sync.aligned.m16n8k16.row.col.f32.f16.f16.f32 "
        "{%0,%1,%2,%3}, {%4,%5,%6,%7}, {%8,%9}, {%0,%1,%2,%3};"
        : "+f"(c[0]), "+f"(c[1]), "+f"(c[2]), "+f"(c[3])
        : "r"(a[0]), "r"(a[1]), "r"(a[2]), "r"(a[3]), "r"(b0), "r"(b1));
}
__device__ __forceinline__ void ldm4(uint32_t* r, uint32_t addr) {
    asm volatile("ldmatrix.sync.aligned.m8n8.x4.shared.b16 {%0,%1,%2,%3}, [%4];"
        : "=r"(r[0]), "=r"(r[1]), "=r"(r[2]), "=r"(r[3]) : "r"(addr));
}
__device__ __forceinline__ uint32_t pack2h(float a, float b) {
    __half2 h = __floats2half2_rn(a, b);
    return *reinterpret_cast<uint32_t*>(&h);
}
__device__ __forceinline__ uint32_t s2u(const void* p) {
    uint32_t a;
    asm("{ .reg .u64 t; cvta.to.shared.u64 t, %1; cvt.u32.u64 %0, t; }" : "=r"(a) : "l"(p));
    return a;
}
__device__ __forceinline__ void cpa16(uint32_t dst, const void* src) {
    asm volatile("cp.async.cg.shared.global [%0], [%1], 16;" :: "r"(dst), "l"(src) : "memory");
}
#define CP_COMMIT() asm volatile("cp.async.commit_group;" ::: "memory")
#define CP_WAIT1()  asm volatile("cp.async.wait_group 1;" ::: "memory")
#define CP_WAIT0()  asm volatile("cp.async.wait_group 0;" ::: "memory")

// ---------------------------------------------------------------------------
// Kernel 0: convert W to fp16, transposed to [n][k].
// ---------------------------------------------------------------------------
__global__ __launch_bounds__(256) void wconv(
    const float* __restrict__ Wk, const float* __restrict__ Wq,
    const float* __restrict__ Wv)
{
    const int n = blockIdx.x;
    const int mat = n >> 6;
    const int col = n & 63;
    const int k4 = threadIdx.x * 4;
    const float* W = (mat == 0) ? Wq : ((mat == 1) ? Wk : Wv);
    float f[4];
#pragma unroll
    for (int j = 0; j < 4; j++) f[j] = W[(size_t)(k4 + j) * H_ + col];
    uint2 p = { pack2h(f[0], f[1]), pack2h(f[2], f[3]) };
    *reinterpret_cast<uint2*>(&g_w[(size_t)n * C_ + k4]) = p;
}

// ---------------------------------------------------------------------------
// Kernel 1: QKV projection, fp16 single-pass mma (R9-proven).
// ---------------------------------------------------------------------------
struct ProjS {
    __half xs[2][64*PK];
    __half ws[2][192*PK];
};

__global__ __launch_bounds__(256, 2) void qkv_proj(const float* __restrict__ x)
{
    extern __shared__ char smraw[];
    ProjS* sm = reinterpret_cast<ProjS*>(smraw);
    const int tid = threadIdx.x, lane = tid & 31, wid = tid >> 5;
    const int g = lane >> 2, tg = lane & 3;
    const int m0 = 32 * (wid >> 2);
    const int n0 = 48 * (wid & 3);
    const size_t rowBase = (size_t)blockIdx.x * 64;

    float acc[2][6][4];
#pragma unroll
    for (int a = 0; a < 2; a++)
#pragma unroll
        for (int b = 0; b < 6; b++)
#pragma unroll
            for (int c = 0; c < 4; c++) acc[a][b][c] = 0.0f;

#pragma unroll
    for (int i = 0; i < 3; i++) {
        int slot = tid + 256*i; int n = slot >> 2; int c8 = (slot & 3) * 8;
        cpa16(s2u(&sm->ws[0][n*PK + c8]), g_w + (size_t)n * C_ + c8);
    }
    CP_COMMIT();
    float4 xr[2];
#pragma unroll
    for (int i = 0; i < 2; i++) {
        int slot = tid + 256*i; int r = slot >> 3; int c = (slot & 7) * 4;
        xr[i] = *(const float4*)(x + (rowBase + r) * C_ + c);
    }

    for (int it = 0; it < 32; ++it) {
        const int s = it & 1;
#pragma unroll
        for (int i = 0; i < 2; i++) {
            int slot = tid + 256*i; int r = slot >> 3; int c = (slot & 7) * 4;
            uint2 p = { pack2h(xr[i].x, xr[i].y), pack2h(xr[i].z, xr[i].w) };
            *reinterpret_cast<uint2*>(&sm->xs[s][r*PK + c]) = p;
        }
        if (it < 31) {
            const int kt = (it + 1) * 32;
#pragma unroll
            for (int i = 0; i < 3; i++) {
                int slot = tid + 256*i; int n = slot >> 2; int c8 = (slot & 3) * 8;
                cpa16(s2u(&sm->ws[1-s][n*PK + c8]), g_w + (size_t)n * C_ + kt + c8);
            }
        }
        CP_COMMIT();
        CP_WAIT1();
        __syncthreads();

        if (it < 31) {
            const int kt = (it + 1) * 32;
#pragma unroll
            for (int i = 0; i < 2; i++) {
                int slot = tid + 256*i; int r = slot >> 3; int c = (slot & 7) * 4;
                xr[i] = *(const float4*)(x + (rowBase + r) * C_ + kt + c);
            }
        }

        const uint32_t* xp = reinterpret_cast<const uint32_t*>(sm->xs[s]);
        const uint32_t* wp = reinterpret_cast<const uint32_t*>(sm->ws[s]);
#pragma unroll
        for (int ks = 0; ks < 2; ks++) {
            const int kw = tg + 8*ks;
            uint32_t ah[2][4];
#pragma unroll
            for (int mt = 0; mt < 2; mt++) {
                int r = m0 + 16*mt + g;
                ah[mt][0] = xp[r*20 + kw];      ah[mt][1] = xp[(r+8)*20 + kw];
                ah[mt][2] = xp[r*20 + kw + 4];  ah[mt][3] = xp[(r+8)*20 + kw + 4];
            }
#pragma unroll
            for (int nt = 0; nt < 6; nt++) {
                int n = n0 + 8*nt + g;
                uint32_t b0 = wp[n*20 + kw], b1 = wp[n*20 + kw + 4];
#pragma unroll
                for (int mt = 0; mt < 2; mt++)
                    mma_f16(acc[mt][nt], ah[mt], b0, b1);
            }
        }
        __syncthreads();
    }

    const float qscale = 0.03125f;
#pragma unroll
    for (int mt = 0; mt < 2; mt++) {
#pragma unroll
        for (int nt = 0; nt < 6; nt++) {
            int gc = n0 + 8*nt;
            float* c = acc[mt][nt];
            int r0 = m0 + 16*mt + g;
            size_t row0 = rowBase + r0, row1 = row0 + 8;
            if (gc < 64) {
                int col = gc + 2*tg;
                *reinterpret_cast<uint32_t*>(&g_q[row0*H_ + col]) = pack2h(c[0]*qscale, c[1]*qscale);
                *reinterpret_cast<uint32_t*>(&g_q[row1*H_ + col]) = pack2h(c[2]*qscale, c[3]*qscale);
            } else if (gc < 128) {
                int col = gc - 64 + 2*tg;
                *reinterpret_cast<uint32_t*>(&g_k[row0*H_ + col]) = pack2h(c[0], c[1]);
                *reinterpret_cast<uint32_t*>(&g_k[row1*H_ + col]) = pack2h(c[2], c[3]);
            } else {
                int h0 = gc - 128 + 2*tg;
                size_t bb = rowBase >> 11;
                size_t tb = (rowBase & 2047);
                g_v[(bb*H_ + h0    )*T_ + tb + r0]     = __float2half_rn(c[0]);
                g_v[(bb*H_ + h0 + 1)*T_ + tb + r0]     = __float2half_rn(c[1]);
                g_v[(bb*H_ + h0    )*T_ + tb + r0 + 8] = __float2half_rn(c[2]);
                g_v[(bb*H_ + h0 + 1)*T_ + tb + r0 + 8] = __float2half_rn(c[3]);
            }
        }
    }
}

// ---------------------------------------------------------------------------
// Kernel 2: 2-way split-KV flash, fp16 1-pass, Q frags in regs, ldmatrix K/V.
// ---------------------------------------------------------------------------
struct FaS {
    __half qh[64*PT];
    __half kh[2][64*PT];
    __half vh[2][64*PT];   // [h][t]
};

__global__ __launch_bounds__(128, 4) void flash_mma()
{
    extern __shared__ char smraw[];
    FaS* sm = reinterpret_cast<FaS*>(smraw);
    const int tid = threadIdx.x, lane = tid & 31;
    const int g = lane >> 2, tg = lane & 3;
    const int m0 = 16 * (tid >> 5);
    const int blk = blockIdx.x;
    const int h    = blk & 1;
    const int rest = blk >> 1;
    const int qt = 31 - (rest >> 3);
    const int b  = rest & 7;
    const int ntiles = (qt >= h) ? ((qt - h) >> 1) + 1 : 0;

    // ldmatrix lane address components (R7 correctness-verified mapping)
    const int arow = (lane & 7) + ((lane >> 3) & 1) * 8;
    const int acol = ((lane >> 4) & 1) * 8;
    const int brow = (lane & 7) + ((lane >> 4) & 1) * 8;
    const int bcol = ((lane >> 3) & 1) * 8;

    const __half* khb = g_k + (size_t)b*T_*H_;
    const __half* vhb = g_v + (size_t)b*H_*T_;

    {
        const __half* sh = g_q + (size_t)(b*T_ + qt*64) * H_;
        const int t0 = h * 64;
#pragma unroll
        for (int i = 0; i < 4; i++) {
            int slot = tid + 128*i; int r = slot >> 3; int c = (slot & 7) * 8;
            cpa16(s2u(&sm->qh[r*PT + c]), sh + r*H_ + c);
            if (ntiles > 0) {
                cpa16(s2u(&sm->kh[0][r*PT + c]), khb + (size_t)(t0 + r)*H_ + c);
                cpa16(s2u(&sm->vh[0][r*PT + c]), vhb + (size_t)r*T_ + t0 + c);
            }
        }
        CP_COMMIT();
    }

    float O[8][4];
#pragma unroll
    for (int a = 0; a < 8; a++)
#pragma unroll
        for (int c = 0; c < 4; c++) O[a][c] = 0.0f;
    float mr[2] = { -1e30f, -1e30f }, lr[2] = { 0.0f, 0.0f };
    uint32_t qf[4][4];   // Q fragments, loaded once at first iteration

    for (int i = 0; i < ntiles; ++i) {
        const int kvt = h + 2*i;
        const int s = i & 1;
        __syncthreads();
        if (i + 1 < ntiles) {
            const int nt4 = (kvt + 2) * 64;
#pragma unroll
            for (int j = 0; j < 4; j++) {
                int slot = tid + 128*j; int r = slot >> 3; int c = (slot & 7) * 8;
                cpa16(s2u(&sm->kh[1-s][r*PT + c]), khb + (size_t)(nt4 + r)*H_ + c);
                cpa16(s2u(&sm->vh[1-s][r*PT + c]), vhb + (size_t)r*T_ + nt4 + c);
            }
        }
        CP_COMMIT();
        CP_WAIT1();
        __syncthreads();

        if (i == 0) {
#pragma unroll
            for (int ks = 0; ks < 4; ks++)
                ldm4(qf[ks], s2u(&sm->qh[(m0 + arow)*PT + ks*16 + acol]));
        }

        float Sf[8][4];
#pragma unroll
        for (int a = 0; a < 8; a++)
#pragma unroll
            for (int c = 0; c < 4; c++) Sf[a][c] = 0.0f;

#pragma unroll
        for (int ks = 0; ks < 4; ks++) {
#pragma unroll
            for (int np = 0; np < 4; np++) {
                uint32_t bh[4];
                ldm4(bh, s2u(&sm->kh[s][(16*np + brow)*PT + ks*16 + bcol]));
                mma_f16(Sf[2*np],     qf[ks], bh[0], bh[1]);
                mma_f16(Sf[2*np + 1], qf[ks], bh[2], bh[3]);
            }
        }

        if (kvt == qt) {
#pragma unroll
            for (int nt = 0; nt < 8; nt++) {
                int colb = 8*nt + 2*tg;
                int row0 = m0 + g, row1 = row0 + 8;
                if (colb     > row0) Sf[nt][0] = -1e30f;
                if (colb + 1 > row0) Sf[nt][1] = -1e30f;
                if (colb     > row1) Sf[nt][2] = -1e30f;
                if (colb + 1 > row1) Sf[nt][3] = -1e30f;
            }
        }

#pragma unroll
        for (int rr = 0; rr < 2; rr++) {
            float mx = -1e30f;
#pragma unroll
            for (int nt = 0; nt < 8; nt++)
                mx = fmaxf(mx, fmaxf(Sf[nt][2*rr], Sf[nt][2*rr+1]));
            mx = fmaxf(mx, __shfl_xor_sync(0xffffffffu, mx, 1));
            mx = fmaxf(mx, __shfl_xor_sync(0xffffffffu, mx, 2));
            float mn = fmaxf(mr[rr], mx);
            float corr = __expf(mr[rr] - mn);
            mr[rr] = mn;
            float sum = 0.0f;
#pragma unroll
            for (int nt = 0; nt < 8; nt++) {
                float p0 = __expf(Sf[nt][2*rr]   - mn);
                float p1 = __expf(Sf[nt][2*rr+1] - mn);
                Sf[nt][2*rr] = p0; Sf[nt][2*rr+1] = p1;
                sum += p0 + p1;
            }
            sum += __shfl_xor_sync(0xffffffffu, sum, 1);
            sum += __shfl_xor_sync(0xffffffffu, sum, 2);
            lr[rr] = lr[rr]*corr + sum;
#pragma unroll
            for (int nt = 0; nt < 8; nt++) {
                O[nt][2*rr]   *= corr;
                O[nt][2*rr+1] *= corr;
            }
        }

#pragma unroll
        for (int ks = 0; ks < 4; ks++) {
            uint32_t ph[4];
            ph[0] = pack2h(Sf[2*ks][0],   Sf[2*ks][1]);
            ph[1] = pack2h(Sf[2*ks][2],   Sf[2*ks][3]);
            ph[2] = pack2h(Sf[2*ks+1][0], Sf[2*ks+1][1]);
            ph[3] = pack2h(Sf[2*ks+1][2], Sf[2*ks+1][3]);
#pragma unroll
            for (int np = 0; np < 4; np++) {
                uint32_t bh[4];
                ldm4(bh, s2u(&sm->vh[s][(16*np + brow)*PT + ks*16 + bcol]));
                mma_f16(O[2*np],     ph, bh[0], bh[1]);
                mma_f16(O[2*np + 1], ph, bh[2], bh[3]);
            }
        }
    }

    CP_WAIT0();

    size_t row0 = (size_t)b*T_ + (size_t)qt*64 + m0 + g;
    size_t row1 = row0 + 8;
    float* Od = g_Om[h];
#pragma unroll
    for (int nt = 0; nt < 8; nt++) {
        int col = 8*nt + 2*tg;
        float2 v0 = { O[nt][0], O[nt][1] };
        float2 v1 = { O[nt][2], O[nt][3] };
        *reinterpret_cast<float2*>(Od + row0*H_ + col) = v0;
        *reinterpret_cast<float2*>(Od + row1*H_ + col) = v1;
    }
    if (tg == 0) {
        g_m[h][row0] = mr[0]; g_l[h][row0] = lr[0];
        g_m[h][row1] = mr[1]; g_l[h][row1] = lr[1];
    }
}

// ---------------------------------------------------------------------------
// Kernel 3: merge — 2 float4 pairs per thread for MLP.
// ---------------------------------------------------------------------------
__global__ __launch_bounds__(256) void fa_merge(float* __restrict__ out)
{
    int idx = blockIdx.x * 256 + threadIdx.x;    // NROW*8 slots
    int row = idx >> 3;
    int c8  = (idx & 7) * 8;
    float m0v = g_m[0][row], m1v = g_m[1][row];
    float l0v = g_l[0][row], l1v = g_l[1][row];
    const float4* p0 = reinterpret_cast<const float4*>(&g_Om[0][(size_t)row*H_ + c8]);
    const float4* p1 = reinterpret_cast<const float4*>(&g_Om[1][(size_t)row*H_ + c8]);
    float4 o0a = p0[0], o0b = p0[1];
    float4 o1a = p1[0], o1b = p1[1];
    float M = fmaxf(m0v, m1v);
    float a0 = __expf(m0v - M), a1 = __expf(m1v - M);
    float inv = 1.0f / (l0v * a0 + l1v * a1);
    float4 ra, rb;
    ra.x = (o0a.x*a0 + o1a.x*a1) * inv;
    ra.y = (o0a.y*a0 + o1a.y*a1) * inv;
    ra.z = (o0a.z*a0 + o1a.z*a1) * inv;
    ra.w = (o0a.w*a0 + o1a.w*a1) * inv;
    rb.x = (o0b.x*a0 + o1b.x*a1) * inv;
    rb.y = (o0b.y*a0 + o1b.y*a1) * inv;
    rb.z = (o0b.z*a0 + o1b.z*a1) * inv;
    rb.w = (o0b.w*a0 + o1b.w*a1) * inv;
    float4* op = reinterpret_cast<float4*>(out + (size_t)row*H_ + c8);
    op[0] = ra;
    op[1] = rb;
}

// ---------------------------------------------------------------------------
extern "C" void kernel_launch(void* const* d_in, const int* in_sizes, int n_in,
                              void* d_out, int out_size)
{
    const float* x  = (const float*)d_in[0];
    const float* Wk = (const float*)d_in[1];
    const float* Wq = (const float*)d_in[2];
    const float* Wv = (const float*)d_in[3];
    float* out = (float*)d_out;

    wconv<<<192, 256>>>(Wk, Wq, Wv);

    const int psm = (int)sizeof(ProjS);   // 40960
    cudaFuncSetAttribute(qkv_proj, cudaFuncAttributeMaxDynamicSharedMemorySize, psm);
    qkv_proj<<<NROW / 64, 256, psm>>>(x);

    const int fsm = (int)sizeof(FaS);     // 46080
    cudaFuncSetAttribute(flash_mma, cudaFuncAttributeMaxDynamicSharedMemorySize, fsm);
    flash_mma<<<(T_/64) * B_ * NSPLIT, 128, fsm>>>();

    fa_merge<<<NROW * 8 / 256, 256>>>(out);
}

// round 11
// speedup vs baseline: 1.8685x; 1.0449x over previous
#include <cuda_runtime.h>
#include <cuda_fp16.h>
#include <cstdint>

#define B_ 8
#define T_ 2048
#define C_ 1024
#define H_ 64
#define NROW (B_*T_)
#define PK 40   // proj smem k-stride (fp16)
#define PT 72   // flash smem stride (fp16)
#define NSPLIT 2

__device__ __half g_w[192*C_];    // [n][k]
__device__ __half g_q[NROW*H_];   // pre-scaled by C^-0.5 * log2(e)
__device__ __half g_k[NROW*H_];
__device__ __half g_v[B_*H_*T_];  // [b][h][t]

__device__ float g_Om[NSPLIT][NROW*H_];
__device__ float g_m[NSPLIT][NROW];
__device__ float g_l[NSPLIT][NROW];
__device__ int   g_cnt[256];      // per-(b,qt) arrival counters (reset each run)

// ---------------------------------------------------------------------------
__device__ __forceinline__ void mma_f16(float* c, const uint32_t* a,
                                        uint32_t b0, uint32_t b1) {
    asm volatile("mma.sync.aligned.m16n8k16.row.col.f32.f16.f16.f32 "
        "{%0,%1,%2,%3}, {%4,%5,%6,%7}, {%8,%9}, {%0,%1,%2,%3};"
        : "+f"(c[0]), "+f"(c[1]), "+f"(c[2]), "+f"(c[3])
        : "r"(a[0]), "r"(a[1]), "r"(a[2]), "r"(a[3]), "r"(b0), "r"(b1));
}
__device__ __forceinline__ void ldm4(uint32_t* r, uint32_t addr) {
    asm volatile("ldmatrix.sync.aligned.m8n8.x4.shared.b16 {%0,%1,%2,%3}, [%4];"
        : "=r"(r[0]), "=r"(r[1]), "=r"(r[2]), "=r"(r[3]) : "r"(addr));
}
__device__ __forceinline__ uint32_t pack2h(float a, float b) {
    __half2 h = __floats2half2_rn(a, b);
    return *reinterpret_cast<uint32_t*>(&h);
}
__device__ __forceinline__ uint32_t s2u(const void* p) {
    uint32_t a;
    asm("{ .reg .u64 t; cvta.to.shared.u64 t, %1; cvt.u32.u64 %0, t; }" : "=r"(a) : "l"(p));
    return a;
}
__device__ __forceinline__ void cpa16(uint32_t dst, const void* src) {
    asm volatile("cp.async.cg.shared.global [%0], [%1], 16;" :: "r"(dst), "l"(src) : "memory");
}
#define CP_COMMIT() asm volatile("cp.async.commit_group;" ::: "memory")
#define CP_WAIT1()  asm volatile("cp.async.wait_group 1;" ::: "memory")
#define CP_WAIT0()  asm volatile("cp.async.wait_group 0;" ::: "memory")

// ---------------------------------------------------------------------------
// Kernel 0: convert W to fp16, transposed to [n][k].
// ---------------------------------------------------------------------------
__global__ __launch_bounds__(256) void wconv(
    const float* __restrict__ Wk, const float* __restrict__ Wq,
    const float* __restrict__ Wv)
{
    const int n = blockIdx.x;
    const int mat = n >> 6;
    const int col = n & 63;
    const int k4 = threadIdx.x * 4;
    const float* W = (mat == 0) ? Wq : ((mat == 1) ? Wk : Wv);
    float f[4];
#pragma unroll
    for (int j = 0; j < 4; j++) f[j] = W[(size_t)(k4 + j) * H_ + col];
    uint2 p = { pack2h(f[0], f[1]), pack2h(f[2], f[3]) };
    *reinterpret_cast<uint2*>(&g_w[(size_t)n * C_ + k4]) = p;
}

// ---------------------------------------------------------------------------
// Kernel 1: QKV projection, fp16 1-pass, 3-stage W ring (single sync/iter).
// ---------------------------------------------------------------------------
struct ProjS {
    __half xs[2][64*PK];
    __half ws[3][192*PK];
};

__global__ __launch_bounds__(256, 2) void qkv_proj(const float* __restrict__ x)
{
    extern __shared__ char smraw[];
    ProjS* sm = reinterpret_cast<ProjS*>(smraw);
    const int tid = threadIdx.x, lane = tid & 31, wid = tid >> 5;
    const int g = lane >> 2, tg = lane & 3;
    const int m0 = 32 * (wid >> 2);
    const int n0 = 48 * (wid & 3);
    const size_t rowBase = (size_t)blockIdx.x * 64;

    float acc[2][6][4];
#pragma unroll
    for (int a = 0; a < 2; a++)
#pragma unroll
        for (int b = 0; b < 6; b++)
#pragma unroll
            for (int c = 0; c < 4; c++) acc[a][b][c] = 0.0f;

    // prologue: W stage 0 via cp.async, x chunk 0 into regs
#pragma unroll
    for (int i = 0; i < 3; i++) {
        int slot = tid + 256*i; int n = slot >> 2; int c8 = (slot & 3) * 8;
        cpa16(s2u(&sm->ws[0][n*PK + c8]), g_w + (size_t)n * C_ + c8);
    }
    CP_COMMIT();
    float4 xr[2];
#pragma unroll
    for (int i = 0; i < 2; i++) {
        int slot = tid + 256*i; int r = slot >> 3; int c = (slot & 7) * 4;
        xr[i] = *(const float4*)(x + (rowBase + r) * C_ + c);
    }

    for (int it = 0; it < 32; ++it) {
        const int sw = it % 3;           // W compute stage
        const int xw = it & 1;           // x compute stage
        // issue next W tile into stage (it+1)%3 (never a stage being read)
        if (it < 31) {
            const int kt = (it + 1) * 32;
            const int wn = (it + 1) % 3;
#pragma unroll
            for (int i = 0; i < 3; i++) {
                int slot = tid + 256*i; int n = slot >> 2; int c8 = (slot & 3) * 8;
                cpa16(s2u(&sm->ws[wn][n*PK + c8]), g_w + (size_t)n * C_ + kt + c8);
            }
        }
        CP_COMMIT();
        CP_WAIT1();
        // convert + store x into stage xw
#pragma unroll
        for (int i = 0; i < 2; i++) {
            int slot = tid + 256*i; int r = slot >> 3; int c = (slot & 7) * 4;
            uint2 p = { pack2h(xr[i].x, xr[i].y), pack2h(xr[i].z, xr[i].w) };
            *reinterpret_cast<uint2*>(&sm->xs[xw][r*PK + c]) = p;
        }
        __syncthreads();   // single barrier: W group + x stores visible to all

        if (it < 31) {
            const int kt = (it + 1) * 32;
#pragma unroll
            for (int i = 0; i < 2; i++) {
                int slot = tid + 256*i; int r = slot >> 3; int c = (slot & 7) * 4;
                xr[i] = *(const float4*)(x + (rowBase + r) * C_ + kt + c);
            }
        }

        const uint32_t* xp = reinterpret_cast<const uint32_t*>(sm->xs[xw]);
        const uint32_t* wp = reinterpret_cast<const uint32_t*>(sm->ws[sw]);
#pragma unroll
        for (int ks = 0; ks < 2; ks++) {
            const int kw = tg + 8*ks;
            uint32_t ah[2][4];
#pragma unroll
            for (int mt = 0; mt < 2; mt++) {
                int r = m0 + 16*mt + g;
                ah[mt][0] = xp[r*20 + kw];      ah[mt][1] = xp[(r+8)*20 + kw];
                ah[mt][2] = xp[r*20 + kw + 4];  ah[mt][3] = xp[(r+8)*20 + kw + 4];
            }
#pragma unroll
            for (int nt = 0; nt < 6; nt++) {
                int n = n0 + 8*nt + g;
                uint32_t b0 = wp[n*20 + kw], b1 = wp[n*20 + kw + 4];
#pragma unroll
                for (int mt = 0; mt < 2; mt++)
                    mma_f16(acc[mt][nt], ah[mt], b0, b1);
            }
        }
        // no trailing sync: next iter writes only stages no warp can still read
    }

    const float qscale = 0.03125f * 1.44269504f;  // C^-0.5 * log2(e)
#pragma unroll
    for (int mt = 0; mt < 2; mt++) {
#pragma unroll
        for (int nt = 0; nt < 6; nt++) {
            int gc = n0 + 8*nt;
            float* c = acc[mt][nt];
            int r0 = m0 + 16*mt + g;
            size_t row0 = rowBase + r0, row1 = row0 + 8;
            if (gc < 64) {
                int col = gc + 2*tg;
                *reinterpret_cast<uint32_t*>(&g_q[row0*H_ + col]) = pack2h(c[0]*qscale, c[1]*qscale);
                *reinterpret_cast<uint32_t*>(&g_q[row1*H_ + col]) = pack2h(c[2]*qscale, c[3]*qscale);
            } else if (gc < 128) {
                int col = gc - 64 + 2*tg;
                *reinterpret_cast<uint32_t*>(&g_k[row0*H_ + col]) = pack2h(c[0], c[1]);
                *reinterpret_cast<uint32_t*>(&g_k[row1*H_ + col]) = pack2h(c[2], c[3]);
            } else {
                int h0 = gc - 128 + 2*tg;
                size_t bb = rowBase >> 11;
                size_t tb = (rowBase & 2047);
                g_v[(bb*H_ + h0    )*T_ + tb + r0]     = __float2half_rn(c[0]);
                g_v[(bb*H_ + h0 + 1)*T_ + tb + r0]     = __float2half_rn(c[1]);
                g_v[(bb*H_ + h0    )*T_ + tb + r0 + 8] = __float2half_rn(c[2]);
                g_v[(bb*H_ + h0 + 1)*T_ + tb + r0 + 8] = __float2half_rn(c[3]);
            }
        }
    }
}

// ---------------------------------------------------------------------------
// Kernel 2: 2-way split-KV flash, exp2-domain softmax, fused atomic merge.
// ---------------------------------------------------------------------------
struct FaS {
    __half qh[64*PT];
    __half kh[2][64*PT];
    __half vh[2][64*PT];   // [h][t]
};

__global__ __launch_bounds__(128, 4) void flash_mma(float* __restrict__ out)
{
    extern __shared__ char smraw[];
    FaS* sm = reinterpret_cast<FaS*>(smraw);
    __shared__ int s_who;
    const int tid = threadIdx.x, lane = tid & 31;
    const int g = lane >> 2, tg = lane & 3;
    const int m0 = 16 * (tid >> 5);
    const int blk = blockIdx.x;
    const int h    = blk & 1;
    const int pid  = blk >> 1;         // 0..255 pair id
    const int qt = 31 - (pid >> 3);
    const int b  = pid & 7;
    const int ntiles = (qt >= h) ? ((qt - h) >> 1) + 1 : 0;

    const int arow = (lane & 7) + ((lane >> 3) & 1) * 8;
    const int acol = ((lane >> 4) & 1) * 8;
    const int brow = (lane & 7) + ((lane >> 4) & 1) * 8;
    const int bcol = ((lane >> 3) & 1) * 8;

    const __half* khb = g_k + (size_t)b*T_*H_;
    const __half* vhb = g_v + (size_t)b*H_*T_;

    {
        const __half* sh = g_q + (size_t)(b*T_ + qt*64) * H_;
        const int t0 = h * 64;
#pragma unroll
        for (int i = 0; i < 4; i++) {
            int slot = tid + 128*i; int r = slot >> 3; int c = (slot & 7) * 8;
            cpa16(s2u(&sm->qh[r*PT + c]), sh + r*H_ + c);
            if (ntiles > 0) {
                cpa16(s2u(&sm->kh[0][r*PT + c]), khb + (size_t)(t0 + r)*H_ + c);
                cpa16(s2u(&sm->vh[0][r*PT + c]), vhb + (size_t)r*T_ + t0 + c);
            }
        }
        CP_COMMIT();
    }

    float O[8][4];
#pragma unroll
    for (int a = 0; a < 8; a++)
#pragma unroll
        for (int c = 0; c < 4; c++) O[a][c] = 0.0f;
    float mr[2] = { -1e30f, -1e30f }, lr[2] = { 0.0f, 0.0f };
    uint32_t qf[4][4];

    for (int i = 0; i < ntiles; ++i) {
        const int kvt = h + 2*i;
        const int s = i & 1;
        __syncthreads();
        if (i + 1 < ntiles) {
            const int nt4 = (kvt + 2) * 64;
#pragma unroll
            for (int j = 0; j < 4; j++) {
                int slot = tid + 128*j; int r = slot >> 3; int c = (slot & 7) * 8;
                cpa16(s2u(&sm->kh[1-s][r*PT + c]), khb + (size_t)(nt4 + r)*H_ + c);
                cpa16(s2u(&sm->vh[1-s][r*PT + c]), vhb + (size_t)r*T_ + nt4 + c);
            }
        }
        CP_COMMIT();
        CP_WAIT1();
        __syncthreads();

        if (i == 0) {
#pragma unroll
            for (int ks = 0; ks < 4; ks++)
                ldm4(qf[ks], s2u(&sm->qh[(m0 + arow)*PT + ks*16 + acol]));
        }

        float Sf[8][4];
#pragma unroll
        for (int a = 0; a < 8; a++)
#pragma unroll
            for (int c = 0; c < 4; c++) Sf[a][c] = 0.0f;

#pragma unroll
        for (int ks = 0; ks < 4; ks++) {
#pragma unroll
            for (int np = 0; np < 4; np++) {
                uint32_t bh[4];
                ldm4(bh, s2u(&sm->kh[s][(16*np + brow)*PT + ks*16 + bcol]));
                mma_f16(Sf[2*np],     qf[ks], bh[0], bh[1]);
                mma_f16(Sf[2*np + 1], qf[ks], bh[2], bh[3]);
            }
        }

        if (kvt == qt) {
#pragma unroll
            for (int nt = 0; nt < 8; nt++) {
                int colb = 8*nt + 2*tg;
                int row0 = m0 + g, row1 = row0 + 8;
                if (colb     > row0) Sf[nt][0] = -1e30f;
                if (colb + 1 > row0) Sf[nt][1] = -1e30f;
                if (colb     > row1) Sf[nt][2] = -1e30f;
                if (colb + 1 > row1) Sf[nt][3] = -1e30f;
            }
        }

#pragma unroll
        for (int rr = 0; rr < 2; rr++) {
            float mx = -1e30f;
#pragma unroll
            for (int nt = 0; nt < 8; nt++)
                mx = fmaxf(mx, fmaxf(Sf[nt][2*rr], Sf[nt][2*rr+1]));
            mx = fmaxf(mx, __shfl_xor_sync(0xffffffffu, mx, 1));
            mx = fmaxf(mx, __shfl_xor_sync(0xffffffffu, mx, 2));
            float mn = fmaxf(mr[rr], mx);
            float corr = exp2f(mr[rr] - mn);
            mr[rr] = mn;
            float sum = 0.0f;
#pragma unroll
            for (int nt = 0; nt < 8; nt++) {
                float p0 = exp2f(Sf[nt][2*rr]   - mn);
                float p1 = exp2f(Sf[nt][2*rr+1] - mn);
                Sf[nt][2*rr] = p0; Sf[nt][2*rr+1] = p1;
                sum += p0 + p1;
            }
            sum += __shfl_xor_sync(0xffffffffu, sum, 1);
            sum += __shfl_xor_sync(0xffffffffu, sum, 2);
            lr[rr] = lr[rr]*corr + sum;
#pragma unroll
            for (int nt = 0; nt < 8; nt++) {
                O[nt][2*rr]   *= corr;
                O[nt][2*rr+1] *= corr;
            }
        }

#pragma unroll
        for (int ks = 0; ks < 4; ks++) {
            uint32_t ph[4];
            ph[0] = pack2h(Sf[2*ks][0],   Sf[2*ks][1]);
            ph[1] = pack2h(Sf[2*ks][2],   Sf[2*ks][3]);
            ph[2] = pack2h(Sf[2*ks+1][0], Sf[2*ks+1][1]);
            ph[3] = pack2h(Sf[2*ks+1][2], Sf[2*ks+1][3]);
#pragma unroll
            for (int np = 0; np < 4; np++) {
                uint32_t bh[4];
                ldm4(bh, s2u(&sm->vh[s][(16*np + brow)*PT + ks*16 + bcol]));
                mma_f16(O[2*np],     ph, bh[0], bh[1]);
                mma_f16(O[2*np + 1], ph, bh[2], bh[3]);
            }
        }
    }

    CP_WAIT0();

    // --- write partial, then arrive; last arriver merges + writes final out ---
    size_t row0 = (size_t)b*T_ + (size_t)qt*64 + m0 + g;
    size_t row1 = row0 + 8;
    float* Od = g_Om[h];
#pragma unroll
    for (int nt = 0; nt < 8; nt++) {
        int col = 8*nt + 2*tg;
        float2 v0 = { O[nt][0], O[nt][1] };
        float2 v1 = { O[nt][2], O[nt][3] };
        *reinterpret_cast<float2*>(Od + row0*H_ + col) = v0;
        *reinterpret_cast<float2*>(Od + row1*H_ + col) = v1;
    }
    if (tg == 0) {
        g_m[h][row0] = mr[0]; g_l[h][row0] = lr[0];
        g_m[h][row1] = mr[1]; g_l[h][row1] = lr[1];
    }
    __threadfence();
    __syncthreads();
    if (tid == 0) s_who = atomicAdd(&g_cnt[pid], 1);
    __syncthreads();

    if (s_who == 1) {
        __threadfence();   // acquire peer's partial
        const int o = 1 - h;
        // index-ordered (split 0 first) for run-to-run bit determinism
        float m0v[2], l0v[2], m1v[2], l1v[2];   // [split] for row0/row1
        m0v[h] = mr[0]; l0v[h] = lr[0]; m1v[h] = mr[1]; l1v[h] = lr[1];
        m0v[o] = g_m[o][row0]; l0v[o] = g_l[o][row0];
        m1v[o] = g_m[o][row1]; l1v[o] = g_l[o][row1];
        float M0 = fmaxf(m0v[0], m0v[1]), M1 = fmaxf(m1v[0], m1v[1]);
        float a00 = exp2f(m0v[0] - M0), a01 = exp2f(m0v[1] - M0);
        float a10 = exp2f(m1v[0] - M1), a11 = exp2f(m1v[1] - M1);
        float inv0 = 1.0f / __fadd_rn(__fmul_rn(l0v[0], a00), __fmul_rn(l0v[1], a01));
        float inv1 = 1.0f / __fadd_rn(__fmul_rn(l1v[0], a10), __fmul_rn(l1v[1], a11));
        const float* Op = g_Om[o];
        // scale factors indexed by split for my regs vs peer
        float s0_mine = (h == 0) ? a00 : a01, s0_peer = (h == 0) ? a01 : a00;
        float s1_mine = (h == 0) ? a10 : a11, s1_peer = (h == 0) ? a11 : a10;
#pragma unroll
        for (int nt = 0; nt < 8; nt++) {
            int col = 8*nt + 2*tg;
            float2 p0 = *reinterpret_cast<const float2*>(Op + row0*H_ + col);
            float2 p1 = *reinterpret_cast<const float2*>(Op + row1*H_ + col);
            float2 r0, r1;
            r0.x = __fmul_rn(__fadd_rn(__fmul_rn(O[nt][0], s0_mine), __fmul_rn(p0.x, s0_peer)), inv0);
            r0.y = __fmul_rn(__fadd_rn(__fmul_rn(O[nt][1], s0_mine), __fmul_rn(p0.y, s0_peer)), inv0);
            r1.x = __fmul_rn(__fadd_rn(__fmul_rn(O[nt][2], s1_mine), __fmul_rn(p1.x, s1_peer)), inv1);
            r1.y = __fmul_rn(__fadd_rn(__fmul_rn(O[nt][3], s1_mine), __fmul_rn(p1.y, s1_peer)), inv1);
            *reinterpret_cast<float2*>(out + row0*H_ + col) = r0;
            *reinterpret_cast<float2*>(out + row1*H_ + col) = r1;
        }
        if (tid == 0) atomicExch(&g_cnt[pid], 0);   // reset for next replay
    }
}

// ---------------------------------------------------------------------------
extern "C" void kernel_launch(void* const* d_in, const int* in_sizes, int n_in,
                              void* d_out, int out_size)
{
    const float* x  = (const float*)d_in[0];
    const float* Wk = (const float*)d_in[1];
    const float* Wq = (const float*)d_in[2];
    const float* Wv = (const float*)d_in[3];
    float* out = (float*)d_out;

    wconv<<<192, 256>>>(Wk, Wq, Wv);

    const int psm = (int)sizeof(ProjS);   // 56320
    cudaFuncSetAttribute(qkv_proj, cudaFuncAttributeMaxDynamicSharedMemorySize, psm);
    qkv_proj<<<NROW / 64, 256, psm>>>(x);

    const int fsm = (int)sizeof(FaS);     // 46080
    cudaFuncSetAttribute(flash_mma, cudaFuncAttributeMaxDynamicSharedMemorySize, fsm);
    flash_mma<<<(T_/64) * B_ * NSPLIT, 128, fsm>>>(out);
}

// round 13
// speedup vs baseline: 1.9091x; 1.0218x over previous
#include <cuda_runtime.h>
#include <cuda_fp16.h>
#include <cstdint>

#define B_ 8
#define T_ 2048
#define C_ 1024
#define H_ 64
#define NROW (B_*T_)
#define PK 40   // proj smem k-stride (fp16)
#define PT 72   // flash smem stride (fp16)
#define NSPLIT 2

__device__ __half g_w[192*C_];    // [n][k]
__device__ __half g_q[NROW*H_];   // pre-scaled by C^-0.5 * log2(e)
__device__ __half g_k[NROW*H_];
__device__ __half g_v[B_*H_*T_];  // [b][h][t]

__device__ float g_Om[NSPLIT][NROW*H_];
__device__ float g_m[NSPLIT][NROW];
__device__ float g_l[NSPLIT][NROW];
__device__ int   g_cnt[256];

// ---------------------------------------------------------------------------
__device__ __forceinline__ void mma_f16(float* c, const uint32_t* a,
                                        uint32_t b0, uint32_t b1) {
    asm volatile("mma.sync.aligned.m16n8k16.row.col.f32.f16.f16.f32 "
        "{%0,%1,%2,%3}, {%4,%5,%6,%7}, {%8,%9}, {%0,%1,%2,%3};"
        : "+f"(c[0]), "+f"(c[1]), "+f"(c[2]), "+f"(c[3])
        : "r"(a[0]), "r"(a[1]), "r"(a[2]), "r"(a[3]), "r"(b0), "r"(b1));
}
__device__ __forceinline__ void ldm4(uint32_t* r, uint32_t addr) {
    asm volatile("ldmatrix.sync.aligned.m8n8.x4.shared.b16 {%0,%1,%2,%3}, [%4];"
        : "=r"(r[0]), "=r"(r[1]), "=r"(r[2]), "=r"(r[3]) : "r"(addr));
}
__device__ __forceinline__ uint32_t pack2h(float a, float b) {
    __half2 h = __floats2half2_rn(a, b);
    return *reinterpret_cast<uint32_t*>(&h);
}
__device__ __forceinline__ uint32_t s2u(const void* p) {
    uint32_t a;
    asm("{ .reg .u64 t; cvta.to.shared.u64 t, %1; cvt.u32.u64 %0, t; }" : "=r"(a) : "l"(p));
    return a;
}
__device__ __forceinline__ void cpa16(uint32_t dst, const void* src) {
    asm volatile("cp.async.cg.shared.global [%0], [%1], 16;" :: "r"(dst), "l"(src) : "memory");
}
#define CP_COMMIT() asm volatile("cp.async.commit_group;" ::: "memory")
#define CP_WAIT1()  asm volatile("cp.async.wait_group 1;" ::: "memory")
#define CP_WAIT0()  asm volatile("cp.async.wait_group 0;" ::: "memory")

// ---------------------------------------------------------------------------
// Kernel 0: W -> fp16 [n][k] via coalesced smem tile transpose.
// Grid 192: block = (mat 0..2)*64 + (ktile 0..63); each handles 16 k x 64 n.
// ---------------------------------------------------------------------------
__global__ __launch_bounds__(256) void wconv(
    const float* __restrict__ Wk, const float* __restrict__ Wq,
    const float* __restrict__ Wv)
{
    __shared__ float tile[16][65];
    const int blk = blockIdx.x;
    const int mat = blk >> 6;              // 0=q,1=k,2=v  (64 blocks per matrix)
    const int kt  = (blk & 63) * 16;       // k base (16 rows), covers 0..1023
    const int tid = threadIdx.x;
    const float* W = (mat == 0) ? Wq : ((mat == 1) ? Wk : Wv);

    // coalesced read: 16 rows x 64 cols, 1 float4/thread
    {
        int r  = tid >> 4;                 // 0..15
        int c4 = (tid & 15) * 4;           // 0..60
        float4 v = *(const float4*)(W + (size_t)(kt + r) * H_ + c4);
        tile[r][c4+0] = v.x; tile[r][c4+1] = v.y;
        tile[r][c4+2] = v.z; tile[r][c4+3] = v.w;
    }
    __syncthreads();

    // transposed write: 1 uint2 (4 halves along k) per thread
    {
        int n0 = tid >> 2;                 // 0..63
        int k4 = (tid & 3) * 4;            // 0..12
        uint2 p = { pack2h(tile[k4+0][n0], tile[k4+1][n0]),
                    pack2h(tile[k4+2][n0], tile[k4+3][n0]) };
        *reinterpret_cast<uint2*>(&g_w[(size_t)(mat*64 + n0) * C_ + kt + k4]) = p;
    }
}

// ---------------------------------------------------------------------------
// Kernel 1: QKV projection, fp16 1-pass, 3-stage W ring (R11-proven).
// ---------------------------------------------------------------------------
struct ProjS {
    __half xs[2][64*PK];
    __half ws[3][192*PK];
};

__global__ __launch_bounds__(256, 2) void qkv_proj(const float* __restrict__ x)
{
    extern __shared__ char smraw[];
    ProjS* sm = reinterpret_cast<ProjS*>(smraw);
    const int tid = threadIdx.x, lane = tid & 31, wid = tid >> 5;
    const int g = lane >> 2, tg = lane & 3;
    const int m0 = 32 * (wid >> 2);
    const int n0 = 48 * (wid & 3);
    const size_t rowBase = (size_t)blockIdx.x * 64;

    float acc[2][6][4];
#pragma unroll
    for (int a = 0; a < 2; a++)
#pragma unroll
        for (int b = 0; b < 6; b++)
#pragma unroll
            for (int c = 0; c < 4; c++) acc[a][b][c] = 0.0f;

#pragma unroll
    for (int i = 0; i < 3; i++) {
        int slot = tid + 256*i; int n = slot >> 2; int c8 = (slot & 3) * 8;
        cpa16(s2u(&sm->ws[0][n*PK + c8]), g_w + (size_t)n * C_ + c8);
    }
    CP_COMMIT();
    float4 xr[2];
#pragma unroll
    for (int i = 0; i < 2; i++) {
        int slot = tid + 256*i; int r = slot >> 3; int c = (slot & 7) * 4;
        xr[i] = *(const float4*)(x + (rowBase + r) * C_ + c);
    }

    for (int it = 0; it < 32; ++it) {
        const int sw = it % 3;
        const int xw = it & 1;
        if (it < 31) {
            const int kt = (it + 1) * 32;
            const int wn = (it + 1) % 3;
#pragma unroll
            for (int i = 0; i < 3; i++) {
                int slot = tid + 256*i; int n = slot >> 2; int c8 = (slot & 3) * 8;
                cpa16(s2u(&sm->ws[wn][n*PK + c8]), g_w + (size_t)n * C_ + kt + c8);
            }
        }
        CP_COMMIT();
        CP_WAIT1();
#pragma unroll
        for (int i = 0; i < 2; i++) {
            int slot = tid + 256*i; int r = slot >> 3; int c = (slot & 7) * 4;
            uint2 p = { pack2h(xr[i].x, xr[i].y), pack2h(xr[i].z, xr[i].w) };
            *reinterpret_cast<uint2*>(&sm->xs[xw][r*PK + c]) = p;
        }
        __syncthreads();

        if (it < 31) {
            const int kt = (it + 1) * 32;
#pragma unroll
            for (int i = 0; i < 2; i++) {
                int slot = tid + 256*i; int r = slot >> 3; int c = (slot & 7) * 4;
                xr[i] = *(const float4*)(x + (rowBase + r) * C_ + kt + c);
            }
        }

        const uint32_t* xp = reinterpret_cast<const uint32_t*>(sm->xs[xw]);
        const uint32_t* wp = reinterpret_cast<const uint32_t*>(sm->ws[sw]);
#pragma unroll
        for (int ks = 0; ks < 2; ks++) {
            const int kw = tg + 8*ks;
            uint32_t ah[2][4];
#pragma unroll
            for (int mt = 0; mt < 2; mt++) {
                int r = m0 + 16*mt + g;
                ah[mt][0] = xp[r*20 + kw];      ah[mt][1] = xp[(r+8)*20 + kw];
                ah[mt][2] = xp[r*20 + kw + 4];  ah[mt][3] = xp[(r+8)*20 + kw + 4];
            }
#pragma unroll
            for (int nt = 0; nt < 6; nt++) {
                int n = n0 + 8*nt + g;
                uint32_t b0 = wp[n*20 + kw], b1 = wp[n*20 + kw + 4];
#pragma unroll
                for (int mt = 0; mt < 2; mt++)
                    mma_f16(acc[mt][nt], ah[mt], b0, b1);
            }
        }
    }

    const float qscale = 0.03125f * 1.44269504f;  // C^-0.5 * log2(e)
#pragma unroll
    for (int mt = 0; mt < 2; mt++) {
#pragma unroll
        for (int nt = 0; nt < 6; nt++) {
            int gc = n0 + 8*nt;
            float* c = acc[mt][nt];
            int r0 = m0 + 16*mt + g;
            size_t row0 = rowBase + r0, row1 = row0 + 8;
            if (gc < 64) {
                int col = gc + 2*tg;
                *reinterpret_cast<uint32_t*>(&g_q[row0*H_ + col]) = pack2h(c[0]*qscale, c[1]*qscale);
                *reinterpret_cast<uint32_t*>(&g_q[row1*H_ + col]) = pack2h(c[2]*qscale, c[3]*qscale);
            } else if (gc < 128) {
                int col = gc - 64 + 2*tg;
                *reinterpret_cast<uint32_t*>(&g_k[row0*H_ + col]) = pack2h(c[0], c[1]);
                *reinterpret_cast<uint32_t*>(&g_k[row1*H_ + col]) = pack2h(c[2], c[3]);
            } else {
                int h0 = gc - 128 + 2*tg;
                size_t bb = rowBase >> 11;
                size_t tb = (rowBase & 2047);
                g_v[(bb*H_ + h0    )*T_ + tb + r0]     = __float2half_rn(c[0]);
                g_v[(bb*H_ + h0 + 1)*T_ + tb + r0]     = __float2half_rn(c[1]);
                g_v[(bb*H_ + h0    )*T_ + tb + r0 + 8] = __float2half_rn(c[2]);
                g_v[(bb*H_ + h0 + 1)*T_ + tb + r0 + 8] = __float2half_rn(c[3]);
            }
        }
    }
}

// ---------------------------------------------------------------------------
// Kernel 2: 2-way split-KV flash, exp2 softmax, fused atomic merge (R11).
// ---------------------------------------------------------------------------
struct FaS {
    __half qh[64*PT];
    __half kh[2][64*PT];
    __half vh[2][64*PT];
};

__global__ __launch_bounds__(128, 4) void flash_mma(float* __restrict__ out)
{
    extern __shared__ char smraw[];
    FaS* sm = reinterpret_cast<FaS*>(smraw);
    __shared__ int s_who;
    const int tid = threadIdx.x, lane = tid & 31;
    const int g = lane >> 2, tg = lane & 3;
    const int m0 = 16 * (tid >> 5);
    const int blk = blockIdx.x;
    const int h    = blk & 1;
    const int pid  = blk >> 1;
    const int qt = 31 - (pid >> 3);
    const int b  = pid & 7;
    const int ntiles = (qt >= h) ? ((qt - h) >> 1) + 1 : 0;

    const int arow = (lane & 7) + ((lane >> 3) & 1) * 8;
    const int acol = ((lane >> 4) & 1) * 8;
    const int brow = (lane & 7) + ((lane >> 4) & 1) * 8;
    const int bcol = ((lane >> 3) & 1) * 8;

    const __half* khb = g_k + (size_t)b*T_*H_;
    const __half* vhb = g_v + (size_t)b*H_*T_;

    {
        const __half* sh = g_q + (size_t)(b*T_ + qt*64) * H_;
        const int t0 = h * 64;
#pragma unroll
        for (int i = 0; i < 4; i++) {
            int slot = tid + 128*i; int r = slot >> 3; int c = (slot & 7) * 8;
            cpa16(s2u(&sm->qh[r*PT + c]), sh + r*H_ + c);
            if (ntiles > 0) {
                cpa16(s2u(&sm->kh[0][r*PT + c]), khb + (size_t)(t0 + r)*H_ + c);
                cpa16(s2u(&sm->vh[0][r*PT + c]), vhb + (size_t)r*T_ + t0 + c);
            }
        }
        CP_COMMIT();
    }

    float O[8][4];
#pragma unroll
    for (int a = 0; a < 8; a++)
#pragma unroll
        for (int c = 0; c < 4; c++) O[a][c] = 0.0f;
    float mr[2] = { -1e30f, -1e30f }, lr[2] = { 0.0f, 0.0f };
    uint32_t qf[4][4];

    for (int i = 0; i < ntiles; ++i) {
        const int kvt = h + 2*i;
        const int s = i & 1;
        if (i) __syncthreads();
        if (i + 1 < ntiles) {
            const int nt4 = (kvt + 2) * 64;
#pragma unroll
            for (int j = 0; j < 4; j++) {
                int slot = tid + 128*j; int r = slot >> 3; int c = (slot & 7) * 8;
                cpa16(s2u(&sm->kh[1-s][r*PT + c]), khb + (size_t)(nt4 + r)*H_ + c);
                cpa16(s2u(&sm->vh[1-s][r*PT + c]), vhb + (size_t)r*T_ + nt4 + c);
            }
        }
        CP_COMMIT();
        CP_WAIT1();
        __syncthreads();

        if (i == 0) {
#pragma unroll
            for (int ks = 0; ks < 4; ks++)
                ldm4(qf[ks], s2u(&sm->qh[(m0 + arow)*PT + ks*16 + acol]));
        }

        float Sf[8][4];
#pragma unroll
        for (int a = 0; a < 8; a++)
#pragma unroll
            for (int c = 0; c < 4; c++) Sf[a][c] = 0.0f;

#pragma unroll
        for (int ks = 0; ks < 4; ks++) {
#pragma unroll
            for (int np = 0; np < 4; np++) {
                uint32_t bh[4];
                ldm4(bh, s2u(&sm->kh[s][(16*np + brow)*PT + ks*16 + bcol]));
                mma_f16(Sf[2*np],     qf[ks], bh[0], bh[1]);
                mma_f16(Sf[2*np + 1], qf[ks], bh[2], bh[3]);
            }
        }

        if (kvt == qt) {
#pragma unroll
            for (int nt = 0; nt < 8; nt++) {
                int colb = 8*nt + 2*tg;
                int row0 = m0 + g, row1 = row0 + 8;
                if (colb     > row0) Sf[nt][0] = -1e30f;
                if (colb + 1 > row0) Sf[nt][1] = -1e30f;
                if (colb     > row1) Sf[nt][2] = -1e30f;
                if (colb + 1 > row1) Sf[nt][3] = -1e30f;
            }
        }

#pragma unroll
        for (int rr = 0; rr < 2; rr++) {
            float mx = -1e30f;
#pragma unroll
            for (int nt = 0; nt < 8; nt++)
                mx = fmaxf(mx, fmaxf(Sf[nt][2*rr], Sf[nt][2*rr+1]));
            mx = fmaxf(mx, __shfl_xor_sync(0xffffffffu, mx, 1));
            mx = fmaxf(mx, __shfl_xor_sync(0xffffffffu, mx, 2));
            float mn = fmaxf(mr[rr], mx);
            float corr = exp2f(mr[rr] - mn);
            mr[rr] = mn;
            float sum = 0.0f;
#pragma unroll
            for (int nt = 0; nt < 8; nt++) {
                float p0 = exp2f(Sf[nt][2*rr]   - mn);
                float p1 = exp2f(Sf[nt][2*rr+1] - mn);
                Sf[nt][2*rr] = p0; Sf[nt][2*rr+1] = p1;
                sum += p0 + p1;
            }
            sum += __shfl_xor_sync(0xffffffffu, sum, 1);
            sum += __shfl_xor_sync(0xffffffffu, sum, 2);
            lr[rr] = lr[rr]*corr + sum;
#pragma unroll
            for (int nt = 0; nt < 8; nt++) {
                O[nt][2*rr]   *= corr;
                O[nt][2*rr+1] *= corr;
            }
        }

#pragma unroll
        for (int ks = 0; ks < 4; ks++) {
            uint32_t ph[4];
            ph[0] = pack2h(Sf[2*ks][0],   Sf[2*ks][1]);
            ph[1] = pack2h(Sf[2*ks][2],   Sf[2*ks][3]);
            ph[2] = pack2h(Sf[2*ks+1][0], Sf[2*ks+1][1]);
            ph[3] = pack2h(Sf[2*ks+1][2], Sf[2*ks+1][3]);
#pragma unroll
            for (int np = 0; np < 4; np++) {
                uint32_t bh[4];
                ldm4(bh, s2u(&sm->vh[s][(16*np + brow)*PT + ks*16 + bcol]));
                mma_f16(O[2*np],     ph, bh[0], bh[1]);
                mma_f16(O[2*np + 1], ph, bh[2], bh[3]);
            }
        }
    }

    CP_WAIT0();

    size_t row0 = (size_t)b*T_ + (size_t)qt*64 + m0 + g;
    size_t row1 = row0 + 8;
    float* Od = g_Om[h];
#pragma unroll
    for (int nt = 0; nt < 8; nt++) {
        int col = 8*nt + 2*tg;
        float2 v0 = { O[nt][0], O[nt][1] };
        float2 v1 = { O[nt][2], O[nt][3] };
        *reinterpret_cast<float2*>(Od + row0*H_ + col) = v0;
        *reinterpret_cast<float2*>(Od + row1*H_ + col) = v1;
    }
    if (tg == 0) {
        g_m[h][row0] = mr[0]; g_l[h][row0] = lr[0];
        g_m[h][row1] = mr[1]; g_l[h][row1] = lr[1];
    }
    __threadfence();
    __syncthreads();
    if (tid == 0) s_who = atomicAdd(&g_cnt[pid], 1);
    __syncthreads();

    if (s_who == 1) {
        __threadfence();
        const int o = 1 - h;
        float m0v[2], l0v[2], m1v[2], l1v[2];
        m0v[h] = mr[0]; l0v[h] = lr[0]; m1v[h] = mr[1]; l1v[h] = lr[1];
        m0v[o] = g_m[o][row0]; l0v[o] = g_l[o][row0];
        m1v[o] = g_m[o][row1]; l1v[o] = g_l[o][row1];
        float M0 = fmaxf(m0v[0], m0v[1]), M1 = fmaxf(m1v[0], m1v[1]);
        float a00 = exp2f(m0v[0] - M0), a01 = exp2f(m0v[1] - M0);
        float a10 = exp2f(m1v[0] - M1), a11 = exp2f(m1v[1] - M1);
        float inv0 = 1.0f / __fadd_rn(__fmul_rn(l0v[0], a00), __fmul_rn(l0v[1], a01));
        float inv1 = 1.0f / __fadd_rn(__fmul_rn(l1v[0], a10), __fmul_rn(l1v[1], a11));
        const float* Op = g_Om[o];
        float s0_mine = (h == 0) ? a00 : a01, s0_peer = (h == 0) ? a01 : a00;
        float s1_mine = (h == 0) ? a10 : a11, s1_peer = (h == 0) ? a11 : a10;
#pragma unroll
        for (int nt = 0; nt < 8; nt++) {
            int col = 8*nt + 2*tg;
            float2 p0 = *reinterpret_cast<const float2*>(Op + row0*H_ + col);
            float2 p1 = *reinterpret_cast<const float2*>(Op + row1*H_ + col);
            float2 r0, r1;
            r0.x = __fmul_rn(__fadd_rn(__fmul_rn(O[nt][0], s0_mine), __fmul_rn(p0.x, s0_peer)), inv0);
            r0.y = __fmul_rn(__fadd_rn(__fmul_rn(O[nt][1], s0_mine), __fmul_rn(p0.y, s0_peer)), inv0);
            r1.x = __fmul_rn(__fadd_rn(__fmul_rn(O[nt][2], s1_mine), __fmul_rn(p1.x, s1_peer)), inv1);
            r1.y = __fmul_rn(__fadd_rn(__fmul_rn(O[nt][3], s1_mine), __fmul_rn(p1.y, s1_peer)), inv1);
            *reinterpret_cast<float2*>(out + row0*H_ + col) = r0;
            *reinterpret_cast<float2*>(out + row1*H_ + col) = r1;
        }
        if (tid == 0) atomicExch(&g_cnt[pid], 0);
    }
}

// ---------------------------------------------------------------------------
extern "C" void kernel_launch(void* const* d_in, const int* in_sizes, int n_in,
                              void* d_out, int out_size)
{
    const float* x  = (const float*)d_in[0];
    const float* Wk = (const float*)d_in[1];
    const float* Wq = (const float*)d_in[2];
    const float* Wv = (const float*)d_in[3];
    float* out = (float*)d_out;

    wconv<<<192, 256>>>(Wk, Wq, Wv);

    const int psm = (int)sizeof(ProjS);   // 56320
    cudaFuncSetAttribute(qkv_proj, cudaFuncAttributeMaxDynamicSharedMemorySize, psm);
    qkv_proj<<<NROW / 64, 256, psm>>>(x);

    const int fsm = (int)sizeof(FaS);     // 46080
    cudaFuncSetAttribute(flash_mma, cudaFuncAttributeMaxDynamicSharedMemorySize, fsm);
    flash_mma<<<(T_/64) * B_ * NSPLIT, 128, fsm>>>(out);
}